// round 5
// baseline (speedup 1.0000x reference)
#include <cuda_runtime.h>
#include <cuda_bf16.h>
#include <math.h>
#include <stdint.h>

#define D_    768
#define P_    2048
#define B_    4
#define H_    12
#define DFF_  3072
#define NTOK  (B_ * P_)      /* 8192 */
#define D3_   (3 * D_)       /* 2304 */
#define EPS_  1e-3f
#define SURV_ 0.9f

// ---------------- scratch (static device globals) ---------------------------
__device__ __nv_bfloat16 g_h_hi [NTOK * D_];
__device__ __nv_bfloat16 g_h_lo [NTOK * D_];
__device__ __nv_bfloat16 g_qkvb [NTOK * D3_];   // bf16 QKV
__device__ float         g_x1   [NTOK * D_];
__device__ __nv_bfloat16 g_ffn_hi[NTOK * DFF_];
__device__ __nv_bfloat16 g_ffn_lo[NTOK * DFF_];
// transposed+split weights: [N, K] layout
__device__ __nv_bfloat16 g_wq_hi[D3_ * D_],  g_wq_lo[D3_ * D_];
__device__ __nv_bfloat16 g_w1_hi[DFF_ * D_], g_w1_lo[DFF_ * D_];
__device__ __nv_bfloat16 g_w2_hi[D_ * DFF_], g_w2_lo[D_ * DFF_];

// ---------------- helpers ----------------------------------------------------
__device__ __forceinline__ uint32_t smem_u32(const void* p) {
    uint32_t a;
    asm("{ .reg .u64 t; cvta.to.shared.u64 t, %1; cvt.u32.u64 %0, t; }"
        : "=r"(a) : "l"(p));
    return a;
}
__device__ __forceinline__ void ldsm_x4(uint32_t* r, uint32_t addr) {
    asm volatile("ldmatrix.sync.aligned.m8n8.x4.shared.b16 {%0,%1,%2,%3}, [%4];"
                 : "=r"(r[0]), "=r"(r[1]), "=r"(r[2]), "=r"(r[3]) : "r"(addr));
}
__device__ __forceinline__ void ldsm_x4_t(uint32_t* r, uint32_t addr) {
    asm volatile("ldmatrix.sync.aligned.m8n8.x4.trans.shared.b16 {%0,%1,%2,%3}, [%4];"
                 : "=r"(r[0]), "=r"(r[1]), "=r"(r[2]), "=r"(r[3]) : "r"(addr));
}
__device__ __forceinline__ void mma16816(float* c, const uint32_t* a,
                                         uint32_t b0, uint32_t b1) {
    asm volatile(
        "mma.sync.aligned.m16n8k16.row.col.f32.bf16.bf16.f32 "
        "{%0,%1,%2,%3}, {%4,%5,%6,%7}, {%8,%9}, {%0,%1,%2,%3};"
        : "+f"(c[0]), "+f"(c[1]), "+f"(c[2]), "+f"(c[3])
        : "r"(a[0]), "r"(a[1]), "r"(a[2]), "r"(a[3]), "r"(b0), "r"(b1));
}
__device__ __forceinline__ float ex2f(float x) {
    float y; asm("ex2.approx.f32 %0, %1;" : "=f"(y) : "f"(x)); return y;
}
__device__ __forceinline__ uint32_t pack_bf16x2(float lo, float hi) {
    uint32_t d;
    asm("cvt.rn.bf16x2.f32 %0, %1, %2;" : "=r"(d) : "f"(hi), "f"(lo));
    return d;
}
__device__ __forceinline__ void cp_async16(uint32_t dst, const void* src) {
    asm volatile("cp.async.cg.shared.global [%0], [%1], 16;"
                 :: "r"(dst), "l"(src));
}
#define CP_COMMIT() asm volatile("cp.async.commit_group;" ::: "memory")
#define CP_WAIT(n)  asm volatile("cp.async.wait_group %0;" :: "n"(n) : "memory")

// ---------------- LayerNorm + split: warp-per-row ----------------------------
__global__ void __launch_bounds__(256) ln_split_kernel(
    const float* __restrict__ x, const float* __restrict__ g,
    const float* __restrict__ b,
    __nv_bfloat16* __restrict__ hi, __nv_bfloat16* __restrict__ lo)
{
    const int row  = blockIdx.x * 8 + (threadIdx.x >> 5);
    const int lane = threadIdx.x & 31;
    const float4* xr = (const float4*)(x + (size_t)row * D_);
    const float4* gv = (const float4*)g;
    const float4* bv = (const float4*)b;

    float4 v[6];
    float s = 0.f;
    #pragma unroll
    for (int k = 0; k < 6; k++) {
        v[k] = xr[lane + 32 * k];
        s += v[k].x + v[k].y + v[k].z + v[k].w;
    }
    #pragma unroll
    for (int o = 16; o; o >>= 1) s += __shfl_xor_sync(0xffffffffu, s, o);
    const float mu = s * (1.0f / D_);

    float q = 0.f;
    #pragma unroll
    for (int k = 0; k < 6; k++) {
        v[k].x -= mu; v[k].y -= mu; v[k].z -= mu; v[k].w -= mu;
        q += v[k].x * v[k].x + v[k].y * v[k].y + v[k].z * v[k].z + v[k].w * v[k].w;
    }
    #pragma unroll
    for (int o = 16; o; o >>= 1) q += __shfl_xor_sync(0xffffffffu, q, o);
    const float rs = rsqrtf(q * (1.0f / D_) + EPS_);

    uint2* hp = (uint2*)(hi + (size_t)row * D_);
    uint2* lp = (uint2*)(lo + (size_t)row * D_);
    #pragma unroll
    for (int k = 0; k < 6; k++) {
        const int i4 = lane + 32 * k;
        float4 gg = gv[i4], bb = bv[i4];
        float o0 = v[k].x * rs * gg.x + bb.x;
        float o1 = v[k].y * rs * gg.y + bb.y;
        float o2 = v[k].z * rs * gg.z + bb.z;
        float o3 = v[k].w * rs * gg.w + bb.w;
        float h0 = __bfloat162float(__float2bfloat16(o0));
        float h1 = __bfloat162float(__float2bfloat16(o1));
        float h2 = __bfloat162float(__float2bfloat16(o2));
        float h3 = __bfloat162float(__float2bfloat16(o3));
        uint2 ph = make_uint2(pack_bf16x2(h0, h1), pack_bf16x2(h2, h3));
        uint2 pl = make_uint2(pack_bf16x2(o0 - h0, o1 - h1),
                              pack_bf16x2(o2 - h2, o3 - h3));
        hp[i4] = ph;
        lp[i4] = pl;
    }
}

// ---------------- weight transpose + split: w[K,N] -> wt_{hi,lo}[N,K] -------
__global__ void __launch_bounds__(256) wsplit_kernel(
    const float* __restrict__ w, __nv_bfloat16* __restrict__ hi,
    __nv_bfloat16* __restrict__ lo, int K, int N)
{
    __shared__ float t[32][33];
    const int n0 = blockIdx.x * 32, k0 = blockIdx.y * 32;
    const int tx = threadIdx.x & 31, ty = threadIdx.x >> 5;
    #pragma unroll
    for (int j = 0; j < 4; j++) {
        int k = ty + j * 8;
        t[k][tx] = w[(size_t)(k0 + k) * N + n0 + tx];
    }
    __syncthreads();
    #pragma unroll
    for (int j = 0; j < 4; j++) {
        int n = ty + j * 8;
        float v = t[tx][n];
        __nv_bfloat16 h = __float2bfloat16(v);
        size_t o = (size_t)(n0 + n) * K + k0 + tx;
        hi[o] = h;
        lo[o] = __float2bfloat16(v - __bfloat162float(h));
    }
}

// ---------------- MMA GEMM, 256x128 tile, cp.async 2-stage ------------------
// C[M,N] = (Ahi+Alo)[M,K] @ (Bhi+Blo)[N,K]^T ; K chunk 32; 512 threads.
// 16 warps: 8(m) x 2(n); warp tile 32x64. acc += hh + hl + lh.
// EPI: 1 bias+GELU->bf16 hi/lo ; 2 bias,*0.9+res->fp32 ; 3 bias->bf16
#define BM    256
#define BN    128
#define BKC   32
#define TA_B  20480     /* 256 rows * 80B */
#define TB_B  10240     /* 128 rows * 80B */
#define STAGEB 61440    /* Ahi + Alo + Bhi + Blo */
#define GEMM_SMEM (2 * STAGEB)

template <int EPI>
__global__ void __launch_bounds__(512, 1) gemm_mma(
    const __nv_bfloat16* __restrict__ Ahi_g, const __nv_bfloat16* __restrict__ Alo_g,
    const __nv_bfloat16* __restrict__ Bhi_g, const __nv_bfloat16* __restrict__ Blo_g,
    const float* __restrict__ bias, const float* __restrict__ res,
    float* __restrict__ Cf,
    __nv_bfloat16* __restrict__ Chi, __nv_bfloat16* __restrict__ Clo,
    int M, int N, int K)
{
    extern __shared__ char dsm[];
    const uint32_t sbase = smem_u32(dsm);

    const int tid  = threadIdx.x;
    const int lane = tid & 31;
    const int wid  = tid >> 5;
    const int wm   = wid & 7;
    const int wn   = wid >> 3;
    const int m0   = blockIdx.y * BM;
    const int n0   = blockIdx.x * BN;

    const int a_row = lane & 15;
    const int a_col = (lane >> 4) << 3;
    const uint32_t offA = (uint32_t)((wm * 32 + a_row) * 80 + a_col * 2);
    const int b_row = (lane & 7) | ((lane >> 4) << 3);
    const int b_col = ((lane >> 3) & 1) << 3;
    const uint32_t offB = (uint32_t)(2 * TA_B + (wn * 64 + b_row) * 80 + b_col * 2);

    float acc[2][8][4];
    #pragma unroll
    for (int i = 0; i < 2; i++)
        #pragma unroll
        for (int j = 0; j < 8; j++)
            #pragma unroll
            for (int k = 0; k < 4; k++) acc[i][j][k] = 0.f;

    const int ldu = K >> 3;
    const uint4* gah = (const uint4*)Ahi_g;
    const uint4* gal = (const uint4*)Alo_g;
    const uint4* gbh = (const uint4*)Bhi_g;
    const uint4* gbl = (const uint4*)Blo_g;

    // A: 1024 uint4/tile -> 2 slots/thread ; B: 512 uint4/tile -> 1 slot/thread
    const int ra0 = tid >> 2,          qa0 = tid & 3;
    const int ra1 = (tid + 512) >> 2,  qa1 = (tid + 512) & 3;
    const int rb  = tid >> 2,          qb  = tid & 3;

    const int nchunks = K / BKC;

    auto issue = [&](int stage, int ch) {
        const int k0u = ch * (BKC / 8);
        const uint32_t so = sbase + (uint32_t)stage * STAGEB;
        {
            uint32_t d = so + (uint32_t)(ra0 * 80 + qa0 * 16);
            cp_async16(d,        gah + (size_t)(m0 + ra0) * ldu + k0u + qa0);
            cp_async16(d + TA_B, gal + (size_t)(m0 + ra0) * ldu + k0u + qa0);
        }
        {
            uint32_t d = so + (uint32_t)(ra1 * 80 + qa1 * 16);
            cp_async16(d,        gah + (size_t)(m0 + ra1) * ldu + k0u + qa1);
            cp_async16(d + TA_B, gal + (size_t)(m0 + ra1) * ldu + k0u + qa1);
        }
        {
            uint32_t d = so + (uint32_t)(2 * TA_B + rb * 80 + qb * 16);
            cp_async16(d,        gbh + (size_t)(n0 + rb) * ldu + k0u + qb);
            cp_async16(d + TB_B, gbl + (size_t)(n0 + rb) * ldu + k0u + qb);
        }
    };

    issue(0, 0);
    CP_COMMIT();

    for (int ch = 0; ch < nchunks; ch++) {
        if (ch + 1 < nchunks) {
            issue((ch + 1) & 1, ch + 1);
            CP_COMMIT();
            CP_WAIT(1);
        } else {
            CP_WAIT(0);
        }
        __syncthreads();

        const uint32_t st  = sbase + (uint32_t)(ch & 1) * STAGEB;
        const uint32_t aHi = st + offA;
        const uint32_t aLo = aHi + TA_B;
        const uint32_t bHi = st + offB;
        const uint32_t bLo = bHi + TB_B;

        #pragma unroll
        for (int ks = 0; ks < BKC; ks += 16) {
            uint32_t ah[2][4], al[2][4];
            #pragma unroll
            for (int mt = 0; mt < 2; mt++) {
                ldsm_x4(ah[mt], aHi + mt * 1280 + ks * 2);
                ldsm_x4(al[mt], aLo + mt * 1280 + ks * 2);
            }
            #pragma unroll
            for (int np = 0; np < 4; np++) {
                uint32_t bh[4], bl[4];
                ldsm_x4(bh, bHi + np * 1280 + ks * 2);
                ldsm_x4(bl, bLo + np * 1280 + ks * 2);
                #pragma unroll
                for (int mt = 0; mt < 2; mt++) {
                    mma16816(acc[mt][2 * np],     ah[mt], bh[0], bh[1]);
                    mma16816(acc[mt][2 * np + 1], ah[mt], bh[2], bh[3]);
                    mma16816(acc[mt][2 * np],     al[mt], bh[0], bh[1]);
                    mma16816(acc[mt][2 * np + 1], al[mt], bh[2], bh[3]);
                    mma16816(acc[mt][2 * np],     ah[mt], bl[0], bl[1]);
                    mma16816(acc[mt][2 * np + 1], ah[mt], bl[2], bl[3]);
                }
            }
        }
        __syncthreads();
    }

    // epilogue
    const int lr = lane >> 2;
    const int lc = (lane & 3) * 2;
    #pragma unroll
    for (int mt = 0; mt < 2; mt++) {
        #pragma unroll
        for (int nt = 0; nt < 8; nt++) {
            #pragma unroll
            for (int hh = 0; hh < 2; hh++) {
                const int gr = m0 + wm * 32 + mt * 16 + lr + hh * 8;
                const int gc = n0 + wn * 64 + nt * 8 + lc;
                float v0 = acc[mt][nt][hh * 2 + 0] + bias[gc];
                float v1 = acc[mt][nt][hh * 2 + 1] + bias[gc + 1];
                const size_t go = (size_t)gr * N + gc;
                if (EPI == 1) {
                    v0 = 0.5f * v0 * (1.0f + erff(v0 * 0.70710678118654752f));
                    v1 = 0.5f * v1 * (1.0f + erff(v1 * 0.70710678118654752f));
                    float h0 = __bfloat162float(__float2bfloat16(v0));
                    float h1 = __bfloat162float(__float2bfloat16(v1));
                    ((uint32_t*)Chi)[go >> 1] = pack_bf16x2(h0, h1);
                    ((uint32_t*)Clo)[go >> 1] = pack_bf16x2(v0 - h0, v1 - h1);
                } else if (EPI == 2) {
                    float2 rr = *(const float2*)&res[go];
                    float2 o2 = make_float2(v0 * SURV_ + rr.x, v1 * SURV_ + rr.y);
                    *(float2*)&Cf[go] = o2;
                } else {  // EPI == 3
                    ((uint32_t*)Chi)[go >> 1] = pack_bf16x2(v0, v1);
                }
            }
        }
    }
}

// ---------------- Flash attention (bf16 MMA, q-tile 128, cp.async K/V) ------
// One CTA per (q_tile 128, head, batch); 256 threads (8 warps, 16 q-rows each).
#define FQT 128
#define KT  64
#define QB_  18432                /* 128 rows * 144B */
#define KB_  9216                 /* 64 rows * 144B */
#define FLASH_SMEM (QB_ + 4 * KB_)   /* Q + 2-stage K + 2-stage V = 55296 */

__global__ void __launch_bounds__(256) flash_mma(
    const __nv_bfloat16* __restrict__ qkv, const float* __restrict__ x,
    float* __restrict__ x1)
{
    extern __shared__ char fsm[];
    const uint32_t sb = smem_u32(fsm);
    const uint32_t sq = sb;

    const int t = threadIdx.x;
    const int lane = t & 31, wid = t >> 5;
    const int qt = blockIdx.x, h = blockIdx.y, b = blockIdx.z;
    const size_t base = (size_t)b * P_ * D3_;
    const int q0 = qt * FQT, hc = h * 64;

    // load Q tile (128x64 bf16)
    #pragma unroll
    for (int i = 0; i < 4; i++) {
        int idx = t + i * 256;
        int r = idx >> 3, c8 = (idx & 7) << 3;
        *(uint4*)(fsm + r * 144 + c8 * 2) =
            *(const uint4*)(qkv + base + (size_t)(q0 + r) * D3_ + hc + c8);
    }

    // K/V cp.async slots: 512 uint4/tile -> 2 per thread
    const int kv_r0 = t >> 3,           kv_c0 = (t & 7) << 3;
    const int kv_r1 = (t + 256) >> 3,   kv_c1 = ((t + 256) & 7) << 3;

    auto issueKV = [&](int stage, int kt) {
        const int k0 = kt * KT;
        const uint32_t kb = sb + QB_ + (uint32_t)stage * KB_;
        const uint32_t vb = sb + QB_ + 2 * KB_ + (uint32_t)stage * KB_;
        cp_async16(kb + kv_r0 * 144 + kv_c0 * 2,
                   qkv + base + (size_t)(k0 + kv_r0) * D3_ + D_ + hc + kv_c0);
        cp_async16(kb + kv_r1 * 144 + kv_c1 * 2,
                   qkv + base + (size_t)(k0 + kv_r1) * D3_ + D_ + hc + kv_c1);
        cp_async16(vb + kv_r0 * 144 + kv_c0 * 2,
                   qkv + base + (size_t)(k0 + kv_r0) * D3_ + 2 * D_ + hc + kv_c0);
        cp_async16(vb + kv_r1 * 144 + kv_c1 * 2,
                   qkv + base + (size_t)(k0 + kv_r1) * D3_ + 2 * D_ + hc + kv_c1);
    };

    issueKV(0, 0);
    CP_COMMIT();
    __syncthreads();

    // preload Q fragments
    uint32_t qf[4][4];
    {
        const int qrow = wid * 16 + (lane & 15);
        const int qc = (lane >> 4) << 3;
        #pragma unroll
        for (int ks = 0; ks < 4; ks++)
            ldsm_x4(qf[ks], sq + qrow * 144 + (ks * 16 + qc) * 2);
    }

    float mrow[2] = {-1e30f, -1e30f};
    float lrow[2] = {0.f, 0.f};
    float o[8][4];
    #pragma unroll
    for (int i = 0; i < 8; i++)
        #pragma unroll
        for (int j = 0; j < 4; j++) o[i][j] = 0.f;

    const float SCL = 0.18033688011112042f;  // (1/8) * log2(e)

    const int krow = (lane & 7) + ((lane >> 4) << 3);
    const int kcol = ((lane >> 3) & 1) << 3;
    const int vrow = (lane & 7) + (((lane >> 3) & 1) << 3);
    const int vcol = (lane >> 4) << 3;

    const int niter = P_ / KT;
    for (int kt = 0; kt < niter; kt++) {
        if (kt + 1 < niter) {
            issueKV((kt + 1) & 1, kt + 1);
            CP_COMMIT();
            CP_WAIT(1);
        } else {
            CP_WAIT(0);
        }
        __syncthreads();

        const uint32_t kst = sb + QB_ + (uint32_t)(kt & 1) * KB_;
        const uint32_t vst = sb + QB_ + 2 * KB_ + (uint32_t)(kt & 1) * KB_;

        // S = Q @ K^T
        float s[8][4];
        #pragma unroll
        for (int i = 0; i < 8; i++)
            #pragma unroll
            for (int j = 0; j < 4; j++) s[i][j] = 0.f;
        #pragma unroll
        for (int ks = 0; ks < 4; ks++) {
            #pragma unroll
            for (int tp = 0; tp < 4; tp++) {
                uint32_t kf[4];
                ldsm_x4(kf, kst + (tp * 16 + krow) * 144 + (ks * 16 + kcol) * 2);
                mma16816(s[2 * tp],     qf[ks], kf[0], kf[1]);
                mma16816(s[2 * tp + 1], qf[ks], kf[2], kf[3]);
            }
        }

        // online softmax
        float pm[2] = {-1e30f, -1e30f};
        #pragma unroll
        for (int nt = 0; nt < 8; nt++) {
            pm[0] = fmaxf(pm[0], fmaxf(s[nt][0], s[nt][1]));
            pm[1] = fmaxf(pm[1], fmaxf(s[nt][2], s[nt][3]));
        }
        #pragma unroll
        for (int w = 0; w < 2; w++) {
            pm[w] = fmaxf(pm[w], __shfl_xor_sync(0xffffffffu, pm[w], 1));
            pm[w] = fmaxf(pm[w], __shfl_xor_sync(0xffffffffu, pm[w], 2));
        }
        float mn[2], f[2], sum[2];
        #pragma unroll
        for (int w = 0; w < 2; w++) {
            mn[w] = fmaxf(mrow[w], pm[w]);
            f[w]  = ex2f((mrow[w] - mn[w]) * SCL);
            sum[w] = 0.f;
        }
        #pragma unroll
        for (int nt = 0; nt < 8; nt++) {
            s[nt][0] = ex2f((s[nt][0] - mn[0]) * SCL);
            s[nt][1] = ex2f((s[nt][1] - mn[0]) * SCL);
            s[nt][2] = ex2f((s[nt][2] - mn[1]) * SCL);
            s[nt][3] = ex2f((s[nt][3] - mn[1]) * SCL);
            sum[0] += s[nt][0] + s[nt][1];
            sum[1] += s[nt][2] + s[nt][3];
        }
        #pragma unroll
        for (int w = 0; w < 2; w++) {
            sum[w] += __shfl_xor_sync(0xffffffffu, sum[w], 1);
            sum[w] += __shfl_xor_sync(0xffffffffu, sum[w], 2);
            lrow[w] = lrow[w] * f[w] + sum[w];
            mrow[w] = mn[w];
        }
        #pragma unroll
        for (int nt = 0; nt < 8; nt++) {
            o[nt][0] *= f[0]; o[nt][1] *= f[0];
            o[nt][2] *= f[1]; o[nt][3] *= f[1];
        }

        // P fragments from S accumulators (layout identity)
        uint32_t pf[4][4];
        #pragma unroll
        for (int ks = 0; ks < 4; ks++) {
            pf[ks][0] = pack_bf16x2(s[2 * ks][0],     s[2 * ks][1]);
            pf[ks][1] = pack_bf16x2(s[2 * ks][2],     s[2 * ks][3]);
            pf[ks][2] = pack_bf16x2(s[2 * ks + 1][0], s[2 * ks + 1][1]);
            pf[ks][3] = pack_bf16x2(s[2 * ks + 1][2], s[2 * ks + 1][3]);
        }

        // O += P @ V
        #pragma unroll
        for (int ks = 0; ks < 4; ks++) {
            #pragma unroll
            for (int tp = 0; tp < 4; tp++) {
                uint32_t vf[4];
                ldsm_x4_t(vf, vst + (ks * 16 + vrow) * 144 + (tp * 16 + vcol) * 2);
                mma16816(o[2 * tp],     pf[ks], vf[0], vf[1]);
                mma16816(o[2 * tp + 1], pf[ks], vf[2], vf[3]);
            }
        }
        __syncthreads();
    }

    // finalize: /l, *0.9, + residual x
    const float inv0 = 1.0f / lrow[0];
    const float inv1 = 1.0f / lrow[1];
    const int r0 = q0 + wid * 16 + (lane >> 2);
    const size_t row0 = ((size_t)b * P_ + r0) * D_ + hc + (lane & 3) * 2;
    const size_t row1 = row0 + 8 * D_;
    #pragma unroll
    for (int nt = 0; nt < 8; nt++) {
        float2 xa = *(const float2*)&x[row0 + nt * 8];
        float2 ra;
        ra.x = o[nt][0] * inv0 * SURV_ + xa.x;
        ra.y = o[nt][1] * inv0 * SURV_ + xa.y;
        *(float2*)&x1[row0 + nt * 8] = ra;
        float2 xb = *(const float2*)&x[row1 + nt * 8];
        float2 rb;
        rb.x = o[nt][2] * inv1 * SURV_ + xb.x;
        rb.y = o[nt][3] * inv1 * SURV_ + xb.y;
        *(float2*)&x1[row1 + nt * 8] = rb;
    }
}

// ---------------- launch ----------------------------------------------------
extern "C" void kernel_launch(void* const* d_in, const int* in_sizes, int n_in,
                              void* d_out, int out_size)
{
    const float* x     = (const float*)d_in[0];
    const float* ln1_g = (const float*)d_in[1];
    const float* ln1_b = (const float*)d_in[2];
    const float* w_qkv = (const float*)d_in[3];
    const float* b_qkv = (const float*)d_in[4];
    const float* ln2_g = (const float*)d_in[5];
    const float* ln2_b = (const float*)d_in[6];
    const float* w1    = (const float*)d_in[7];
    const float* b1    = (const float*)d_in[8];
    const float* w2    = (const float*)d_in[9];
    const float* b2    = (const float*)d_in[10];
    float* out = (float*)d_out;

    __nv_bfloat16 *h_hi, *h_lo, *qkvb, *ffn_hi, *ffn_lo;
    __nv_bfloat16 *wq_hi, *wq_lo, *w1_hi, *w1_lo, *w2_hi, *w2_lo;
    float *x1;
    cudaGetSymbolAddress((void**)&h_hi,   g_h_hi);
    cudaGetSymbolAddress((void**)&h_lo,   g_h_lo);
    cudaGetSymbolAddress((void**)&qkvb,   g_qkvb);
    cudaGetSymbolAddress((void**)&x1,     g_x1);
    cudaGetSymbolAddress((void**)&ffn_hi, g_ffn_hi);
    cudaGetSymbolAddress((void**)&ffn_lo, g_ffn_lo);
    cudaGetSymbolAddress((void**)&wq_hi,  g_wq_hi);
    cudaGetSymbolAddress((void**)&wq_lo,  g_wq_lo);
    cudaGetSymbolAddress((void**)&w1_hi,  g_w1_hi);
    cudaGetSymbolAddress((void**)&w1_lo,  g_w1_lo);
    cudaGetSymbolAddress((void**)&w2_hi,  g_w2_hi);
    cudaGetSymbolAddress((void**)&w2_lo,  g_w2_lo);

    cudaFuncSetAttribute(gemm_mma<1>,
                         cudaFuncAttributeMaxDynamicSharedMemorySize, GEMM_SMEM);
    cudaFuncSetAttribute(gemm_mma<2>,
                         cudaFuncAttributeMaxDynamicSharedMemorySize, GEMM_SMEM);
    cudaFuncSetAttribute(gemm_mma<3>,
                         cudaFuncAttributeMaxDynamicSharedMemorySize, GEMM_SMEM);
    cudaFuncSetAttribute(flash_mma,
                         cudaFuncAttributeMaxDynamicSharedMemorySize, FLASH_SMEM);

    // weight transpose + split
    wsplit_kernel<<<dim3(D3_ / 32, D_ / 32), 256>>>(w_qkv, wq_hi, wq_lo, D_, D3_);
    wsplit_kernel<<<dim3(DFF_ / 32, D_ / 32), 256>>>(w1, w1_hi, w1_lo, D_, DFF_);
    wsplit_kernel<<<dim3(D_ / 32, DFF_ / 32), 256>>>(w2, w2_hi, w2_lo, DFF_, D_);

    // 1) LN1 -> split bf16
    ln_split_kernel<<<NTOK / 8, 256>>>(x, ln1_g, ln1_b, h_hi, h_lo);
    // 2) QKV projection -> bf16
    gemm_mma<3><<<dim3(D3_ / BN, NTOK / BM), 512, GEMM_SMEM>>>(
        h_hi, h_lo, wq_hi, wq_lo, b_qkv, nullptr,
        nullptr, qkvb, nullptr, NTOK, D3_, D_);
    // 3) attention + residual -> x1
    flash_mma<<<dim3(P_ / FQT, H_, B_), 256, FLASH_SMEM>>>(qkvb, x, x1);
    // 4) LN2 -> split bf16
    ln_split_kernel<<<NTOK / 8, 256>>>(x1, ln2_g, ln2_b, h_hi, h_lo);
    // 5) MLP up + GELU -> split bf16
    gemm_mma<1><<<dim3(DFF_ / BN, NTOK / BM), 512, GEMM_SMEM>>>(
        h_hi, h_lo, w1_hi, w1_lo, b1, nullptr,
        nullptr, ffn_hi, ffn_lo, NTOK, DFF_, D_);
    // 6) MLP down + droppath + residual -> out
    gemm_mma<2><<<dim3(D_ / BN, NTOK / BM), 512, GEMM_SMEM>>>(
        ffn_hi, ffn_lo, w2_hi, w2_lo, b2, x1,
        out, nullptr, nullptr, NTOK, D_, DFF_);
}

// round 6
// speedup vs baseline: 1.1493x; 1.1493x over previous
#include <cuda_runtime.h>
#include <cuda_bf16.h>
#include <math.h>
#include <stdint.h>

#define D_    768
#define P_    2048
#define B_    4
#define H_    12
#define DFF_  3072
#define NTOK  (B_ * P_)      /* 8192 */
#define D3_   (3 * D_)       /* 2304 */
#define EPS_  1e-3f
#define SURV_ 0.9f

// ---------------- scratch (static device globals) ---------------------------
__device__ __nv_bfloat16 g_h_hi [NTOK * D_];
__device__ __nv_bfloat16 g_h_lo [NTOK * D_];
__device__ __nv_bfloat16 g_qkvb [NTOK * D3_];   // bf16 QKV
__device__ float         g_x1   [NTOK * D_];
__device__ __nv_bfloat16 g_ffn_hi[NTOK * DFF_];
__device__ __nv_bfloat16 g_ffn_lo[NTOK * DFF_];
// transposed+split weights: [N, K] layout
__device__ __nv_bfloat16 g_wq_hi[D3_ * D_],  g_wq_lo[D3_ * D_];
__device__ __nv_bfloat16 g_w1_hi[DFF_ * D_], g_w1_lo[DFF_ * D_];
__device__ __nv_bfloat16 g_w2_hi[D_ * DFF_], g_w2_lo[D_ * DFF_];

// ---------------- helpers ----------------------------------------------------
__device__ __forceinline__ uint32_t smem_u32(const void* p) {
    uint32_t a;
    asm("{ .reg .u64 t; cvta.to.shared.u64 t, %1; cvt.u32.u64 %0, t; }"
        : "=r"(a) : "l"(p));
    return a;
}
__device__ __forceinline__ void ldsm_x4(uint32_t* r, uint32_t addr) {
    asm volatile("ldmatrix.sync.aligned.m8n8.x4.shared.b16 {%0,%1,%2,%3}, [%4];"
                 : "=r"(r[0]), "=r"(r[1]), "=r"(r[2]), "=r"(r[3]) : "r"(addr));
}
__device__ __forceinline__ void ldsm_x4_t(uint32_t* r, uint32_t addr) {
    asm volatile("ldmatrix.sync.aligned.m8n8.x4.trans.shared.b16 {%0,%1,%2,%3}, [%4];"
                 : "=r"(r[0]), "=r"(r[1]), "=r"(r[2]), "=r"(r[3]) : "r"(addr));
}
__device__ __forceinline__ void mma16816(float* c, const uint32_t* a,
                                         uint32_t b0, uint32_t b1) {
    asm volatile(
        "mma.sync.aligned.m16n8k16.row.col.f32.bf16.bf16.f32 "
        "{%0,%1,%2,%3}, {%4,%5,%6,%7}, {%8,%9}, {%0,%1,%2,%3};"
        : "+f"(c[0]), "+f"(c[1]), "+f"(c[2]), "+f"(c[3])
        : "r"(a[0]), "r"(a[1]), "r"(a[2]), "r"(a[3]), "r"(b0), "r"(b1));
}
__device__ __forceinline__ float ex2f(float x) {
    float y; asm("ex2.approx.f32 %0, %1;" : "=f"(y) : "f"(x)); return y;
}
__device__ __forceinline__ uint32_t pack_bf16x2(float lo, float hi) {
    uint32_t d;
    asm("cvt.rn.bf16x2.f32 %0, %1, %2;" : "=r"(d) : "f"(hi), "f"(lo));
    return d;
}
__device__ __forceinline__ void cp_async16(uint32_t dst, const void* src) {
    asm volatile("cp.async.cg.shared.global [%0], [%1], 16;"
                 :: "r"(dst), "l"(src));
}
#define CP_COMMIT() asm volatile("cp.async.commit_group;" ::: "memory")
#define CP_WAIT(n)  asm volatile("cp.async.wait_group %0;" :: "n"(n) : "memory")

// ---------------- LayerNorm + split: warp-per-row ----------------------------
__global__ void __launch_bounds__(256) ln_split_kernel(
    const float* __restrict__ x, const float* __restrict__ g,
    const float* __restrict__ b,
    __nv_bfloat16* __restrict__ hi, __nv_bfloat16* __restrict__ lo)
{
    const int row  = blockIdx.x * 8 + (threadIdx.x >> 5);
    const int lane = threadIdx.x & 31;
    const float4* xr = (const float4*)(x + (size_t)row * D_);
    const float4* gv = (const float4*)g;
    const float4* bv = (const float4*)b;

    float4 v[6];
    float s = 0.f;
    #pragma unroll
    for (int k = 0; k < 6; k++) {
        v[k] = xr[lane + 32 * k];
        s += v[k].x + v[k].y + v[k].z + v[k].w;
    }
    #pragma unroll
    for (int o = 16; o; o >>= 1) s += __shfl_xor_sync(0xffffffffu, s, o);
    const float mu = s * (1.0f / D_);

    float q = 0.f;
    #pragma unroll
    for (int k = 0; k < 6; k++) {
        v[k].x -= mu; v[k].y -= mu; v[k].z -= mu; v[k].w -= mu;
        q += v[k].x * v[k].x + v[k].y * v[k].y + v[k].z * v[k].z + v[k].w * v[k].w;
    }
    #pragma unroll
    for (int o = 16; o; o >>= 1) q += __shfl_xor_sync(0xffffffffu, q, o);
    const float rs = rsqrtf(q * (1.0f / D_) + EPS_);

    uint2* hp = (uint2*)(hi + (size_t)row * D_);
    uint2* lp = (uint2*)(lo + (size_t)row * D_);
    #pragma unroll
    for (int k = 0; k < 6; k++) {
        const int i4 = lane + 32 * k;
        float4 gg = gv[i4], bb = bv[i4];
        float o0 = v[k].x * rs * gg.x + bb.x;
        float o1 = v[k].y * rs * gg.y + bb.y;
        float o2 = v[k].z * rs * gg.z + bb.z;
        float o3 = v[k].w * rs * gg.w + bb.w;
        float h0 = __bfloat162float(__float2bfloat16(o0));
        float h1 = __bfloat162float(__float2bfloat16(o1));
        float h2 = __bfloat162float(__float2bfloat16(o2));
        float h3 = __bfloat162float(__float2bfloat16(o3));
        uint2 ph = make_uint2(pack_bf16x2(h0, h1), pack_bf16x2(h2, h3));
        uint2 pl = make_uint2(pack_bf16x2(o0 - h0, o1 - h1),
                              pack_bf16x2(o2 - h2, o3 - h3));
        hp[i4] = ph;
        lp[i4] = pl;
    }
}

// ---------------- weight transpose + split: w[K,N] -> wt_{hi,lo}[N,K] -------
__global__ void __launch_bounds__(256) wsplit_kernel(
    const float* __restrict__ w, __nv_bfloat16* __restrict__ hi,
    __nv_bfloat16* __restrict__ lo, int K, int N)
{
    __shared__ float t[32][33];
    const int n0 = blockIdx.x * 32, k0 = blockIdx.y * 32;
    const int tx = threadIdx.x & 31, ty = threadIdx.x >> 5;
    #pragma unroll
    for (int j = 0; j < 4; j++) {
        int k = ty + j * 8;
        t[k][tx] = w[(size_t)(k0 + k) * N + n0 + tx];
    }
    __syncthreads();
    #pragma unroll
    for (int j = 0; j < 4; j++) {
        int n = ty + j * 8;
        float v = t[tx][n];
        __nv_bfloat16 h = __float2bfloat16(v);
        size_t o = (size_t)(n0 + n) * K + k0 + tx;
        hi[o] = h;
        lo[o] = __float2bfloat16(v - __bfloat162float(h));
    }
}

// ---------------- MMA GEMM with cp.async 2-stage pipeline (R4 config) -------
// C[M,N] = (Ahi+Alo)[M,K] @ (Bhi+Blo)[N,K]^T ; 128x128 tile, K chunk 32.
// 8 warps (4m x 2n), warp = 32x64. acc += hh + hl + lh. 2 CTAs/SM.
// EPI: 1 bias+GELU->bf16 hi/lo ; 2 bias,*0.9+res->fp32 ; 3 bias->bf16
#define BM   128
#define BN   128
#define BKC  32
#define TILEB 10240       /* 128 * 80 bytes */
#define STAGEB 40960      /* 4 tiles */
#define GEMM_SMEM (2 * STAGEB)

template <int EPI>
__global__ void __launch_bounds__(256, 2) gemm_mma(
    const __nv_bfloat16* __restrict__ Ahi_g, const __nv_bfloat16* __restrict__ Alo_g,
    const __nv_bfloat16* __restrict__ Bhi_g, const __nv_bfloat16* __restrict__ Blo_g,
    const float* __restrict__ bias, const float* __restrict__ res,
    float* __restrict__ Cf,
    __nv_bfloat16* __restrict__ Chi, __nv_bfloat16* __restrict__ Clo,
    int M, int N, int K)
{
    extern __shared__ char dsm[];
    const uint32_t sbase = smem_u32(dsm);

    const int tid  = threadIdx.x;
    const int lane = tid & 31;
    const int wid  = tid >> 5;
    const int wm   = wid & 3;
    const int wn   = wid >> 2;
    const int m0   = blockIdx.y * BM;
    const int n0   = blockIdx.x * BN;

    const int a_row = lane & 15;
    const int a_col = (lane >> 4) << 3;
    const uint32_t offA = (uint32_t)((wm * 32 + a_row) * 80 + a_col * 2);
    const int b_row = (lane & 7) | ((lane >> 4) << 3);
    const int b_col = ((lane >> 3) & 1) << 3;
    const uint32_t offB = (uint32_t)(20480 + (wn * 64 + b_row) * 80 + b_col * 2);

    float acc[2][8][4];
    #pragma unroll
    for (int i = 0; i < 2; i++)
        #pragma unroll
        for (int j = 0; j < 8; j++)
            #pragma unroll
            for (int k = 0; k < 4; k++) acc[i][j][k] = 0.f;

    const int ldu = K >> 3;
    const uint4* gah = (const uint4*)Ahi_g;
    const uint4* gal = (const uint4*)Alo_g;
    const uint4* gbh = (const uint4*)Bhi_g;
    const uint4* gbl = (const uint4*)Blo_g;

    const int r_0 = tid >> 2,         q_0 = tid & 3;
    const int r_1 = (tid + 256) >> 2, q_1 = (tid + 256) & 3;

    const int nchunks = K / BKC;

    auto issue = [&](int stage, int ch) {
        const int k0u = ch * (BKC / 8);
        const uint32_t so = sbase + (uint32_t)stage * STAGEB;
        {
            uint32_t d = so + (uint32_t)(r_0 * 80 + q_0 * 16);
            cp_async16(d,             gah + (size_t)(m0 + r_0) * ldu + k0u + q_0);
            cp_async16(d + TILEB,     gal + (size_t)(m0 + r_0) * ldu + k0u + q_0);
            cp_async16(d + 2 * TILEB, gbh + (size_t)(n0 + r_0) * ldu + k0u + q_0);
            cp_async16(d + 3 * TILEB, gbl + (size_t)(n0 + r_0) * ldu + k0u + q_0);
        }
        {
            uint32_t d = so + (uint32_t)(r_1 * 80 + q_1 * 16);
            cp_async16(d,             gah + (size_t)(m0 + r_1) * ldu + k0u + q_1);
            cp_async16(d + TILEB,     gal + (size_t)(m0 + r_1) * ldu + k0u + q_1);
            cp_async16(d + 2 * TILEB, gbh + (size_t)(n0 + r_1) * ldu + k0u + q_1);
            cp_async16(d + 3 * TILEB, gbl + (size_t)(n0 + r_1) * ldu + k0u + q_1);
        }
    };

    issue(0, 0);
    CP_COMMIT();

    for (int ch = 0; ch < nchunks; ch++) {
        if (ch + 1 < nchunks) {
            issue((ch + 1) & 1, ch + 1);
            CP_COMMIT();
            CP_WAIT(1);
        } else {
            CP_WAIT(0);
        }
        __syncthreads();

        const uint32_t st = sbase + (uint32_t)(ch & 1) * STAGEB;
        const uint32_t aHi = st + offA;
        const uint32_t aLo = aHi + TILEB;
        const uint32_t bHi = st + offB;
        const uint32_t bLo = bHi + TILEB;

        #pragma unroll
        for (int ks = 0; ks < BKC; ks += 16) {
            uint32_t ah[2][4], al[2][4];
            #pragma unroll
            for (int mt = 0; mt < 2; mt++) {
                ldsm_x4(ah[mt], aHi + mt * 1280 + ks * 2);
                ldsm_x4(al[mt], aLo + mt * 1280 + ks * 2);
            }
            #pragma unroll
            for (int np = 0; np < 4; np++) {
                uint32_t bh[4], bl[4];
                ldsm_x4(bh, bHi + np * 1280 + ks * 2);
                ldsm_x4(bl, bLo + np * 1280 + ks * 2);
                #pragma unroll
                for (int mt = 0; mt < 2; mt++) {
                    mma16816(acc[mt][2 * np],     ah[mt], bh[0], bh[1]);
                    mma16816(acc[mt][2 * np + 1], ah[mt], bh[2], bh[3]);
                    mma16816(acc[mt][2 * np],     al[mt], bh[0], bh[1]);
                    mma16816(acc[mt][2 * np + 1], al[mt], bh[2], bh[3]);
                    mma16816(acc[mt][2 * np],     ah[mt], bl[0], bl[1]);
                    mma16816(acc[mt][2 * np + 1], ah[mt], bl[2], bl[3]);
                }
            }
        }
        __syncthreads();
    }

    // epilogue
    const int lr = lane >> 2;
    const int lc = (lane & 3) * 2;
    #pragma unroll
    for (int mt = 0; mt < 2; mt++) {
        #pragma unroll
        for (int nt = 0; nt < 8; nt++) {
            #pragma unroll
            for (int hh = 0; hh < 2; hh++) {
                const int gr = m0 + wm * 32 + mt * 16 + lr + hh * 8;
                const int gc = n0 + wn * 64 + nt * 8 + lc;
                float v0 = acc[mt][nt][hh * 2 + 0] + bias[gc];
                float v1 = acc[mt][nt][hh * 2 + 1] + bias[gc + 1];
                const size_t go = (size_t)gr * N + gc;
                if (EPI == 1) {
                    v0 = 0.5f * v0 * (1.0f + erff(v0 * 0.70710678118654752f));
                    v1 = 0.5f * v1 * (1.0f + erff(v1 * 0.70710678118654752f));
                    float h0 = __bfloat162float(__float2bfloat16(v0));
                    float h1 = __bfloat162float(__float2bfloat16(v1));
                    ((uint32_t*)Chi)[go >> 1] = pack_bf16x2(h0, h1);
                    ((uint32_t*)Clo)[go >> 1] = pack_bf16x2(v0 - h0, v1 - h1);
                } else if (EPI == 2) {
                    float2 rr = *(const float2*)&res[go];
                    float2 o2 = make_float2(v0 * SURV_ + rr.x, v1 * SURV_ + rr.y);
                    *(float2*)&Cf[go] = o2;
                } else {  // EPI == 3
                    ((uint32_t*)Chi)[go >> 1] = pack_bf16x2(v0, v1);
                }
            }
        }
    }
}

// ---------------- Flash attention (bf16 MMA, q-tile 64, cp.async K/V) -------
// One CTA per (q_tile 64, head, batch); 128 threads (4 warps, 16 q-rows each).
#define FQT 64
#define KT  64
#define QB_  9216                  /* 64 rows * 144B */
#define KB_  9216
#define FLASH_SMEM (QB_ + 4 * KB_) /* Q + 2-stage K + 2-stage V = 46080 */

__global__ void __launch_bounds__(128) flash_mma(
    const __nv_bfloat16* __restrict__ qkv, const float* __restrict__ x,
    float* __restrict__ x1)
{
    extern __shared__ char fsm[];
    const uint32_t sb = smem_u32(fsm);

    const int t = threadIdx.x;
    const int lane = t & 31, wid = t >> 5;
    const int qt = blockIdx.x, h = blockIdx.y, b = blockIdx.z;
    const size_t base = (size_t)b * P_ * D3_;
    const int q0 = qt * FQT, hc = h * 64;

    // load Q tile (64x64 bf16), 512 uint4 -> 4 per thread
    #pragma unroll
    for (int i = 0; i < 4; i++) {
        int idx = t + i * 128;
        int r = idx >> 3, c8 = (idx & 7) << 3;
        *(uint4*)(fsm + r * 144 + c8 * 2) =
            *(const uint4*)(qkv + base + (size_t)(q0 + r) * D3_ + hc + c8);
    }

    // K/V cp.async: 512 uint4 per tile -> 4 per thread
    auto issueKV = [&](int stage, int kt) {
        const int k0 = kt * KT;
        const uint32_t kb = sb + QB_ + (uint32_t)stage * KB_;
        const uint32_t vb = sb + QB_ + 2 * KB_ + (uint32_t)stage * KB_;
        #pragma unroll
        for (int i = 0; i < 4; i++) {
            int idx = t + i * 128;
            int r = idx >> 3, c8 = (idx & 7) << 3;
            cp_async16(kb + r * 144 + c8 * 2,
                       qkv + base + (size_t)(k0 + r) * D3_ + D_ + hc + c8);
            cp_async16(vb + r * 144 + c8 * 2,
                       qkv + base + (size_t)(k0 + r) * D3_ + 2 * D_ + hc + c8);
        }
    };

    issueKV(0, 0);
    CP_COMMIT();
    __syncthreads();

    // preload Q fragments (constant across kt)
    uint32_t qf[4][4];
    {
        const int qrow = wid * 16 + (lane & 15);
        const int qc = (lane >> 4) << 3;
        #pragma unroll
        for (int ks = 0; ks < 4; ks++)
            ldsm_x4(qf[ks], sb + qrow * 144 + (ks * 16 + qc) * 2);
    }

    float mrow[2] = {-1e30f, -1e30f};
    float lrow[2] = {0.f, 0.f};
    float o[8][4];
    #pragma unroll
    for (int i = 0; i < 8; i++)
        #pragma unroll
        for (int j = 0; j < 4; j++) o[i][j] = 0.f;

    const float SCL = 0.18033688011112042f;  // (1/8) * log2(e)

    const int krow = (lane & 7) + ((lane >> 4) << 3);
    const int kcol = ((lane >> 3) & 1) << 3;
    const int vrow = (lane & 7) + (((lane >> 3) & 1) << 3);
    const int vcol = (lane >> 4) << 3;

    const int niter = P_ / KT;
    for (int kt = 0; kt < niter; kt++) {
        if (kt + 1 < niter) {
            issueKV((kt + 1) & 1, kt + 1);
            CP_COMMIT();
            CP_WAIT(1);
        } else {
            CP_WAIT(0);
        }
        __syncthreads();

        const uint32_t kst = sb + QB_ + (uint32_t)(kt & 1) * KB_;
        const uint32_t vst = sb + QB_ + 2 * KB_ + (uint32_t)(kt & 1) * KB_;

        // S = Q @ K^T
        float s[8][4];
        #pragma unroll
        for (int i = 0; i < 8; i++)
            #pragma unroll
            for (int j = 0; j < 4; j++) s[i][j] = 0.f;
        #pragma unroll
        for (int ks = 0; ks < 4; ks++) {
            #pragma unroll
            for (int tp = 0; tp < 4; tp++) {
                uint32_t kf[4];
                ldsm_x4(kf, kst + (tp * 16 + krow) * 144 + (ks * 16 + kcol) * 2);
                mma16816(s[2 * tp],     qf[ks], kf[0], kf[1]);
                mma16816(s[2 * tp + 1], qf[ks], kf[2], kf[3]);
            }
        }

        // online softmax
        float pm[2] = {-1e30f, -1e30f};
        #pragma unroll
        for (int nt = 0; nt < 8; nt++) {
            pm[0] = fmaxf(pm[0], fmaxf(s[nt][0], s[nt][1]));
            pm[1] = fmaxf(pm[1], fmaxf(s[nt][2], s[nt][3]));
        }
        #pragma unroll
        for (int w = 0; w < 2; w++) {
            pm[w] = fmaxf(pm[w], __shfl_xor_sync(0xffffffffu, pm[w], 1));
            pm[w] = fmaxf(pm[w], __shfl_xor_sync(0xffffffffu, pm[w], 2));
        }
        float mn[2], f[2], sum[2];
        #pragma unroll
        for (int w = 0; w < 2; w++) {
            mn[w] = fmaxf(mrow[w], pm[w]);
            f[w]  = ex2f((mrow[w] - mn[w]) * SCL);
            sum[w] = 0.f;
        }
        #pragma unroll
        for (int nt = 0; nt < 8; nt++) {
            s[nt][0] = ex2f((s[nt][0] - mn[0]) * SCL);
            s[nt][1] = ex2f((s[nt][1] - mn[0]) * SCL);
            s[nt][2] = ex2f((s[nt][2] - mn[1]) * SCL);
            s[nt][3] = ex2f((s[nt][3] - mn[1]) * SCL);
            sum[0] += s[nt][0] + s[nt][1];
            sum[1] += s[nt][2] + s[nt][3];
        }
        #pragma unroll
        for (int w = 0; w < 2; w++) {
            sum[w] += __shfl_xor_sync(0xffffffffu, sum[w], 1);
            sum[w] += __shfl_xor_sync(0xffffffffu, sum[w], 2);
            lrow[w] = lrow[w] * f[w] + sum[w];
            mrow[w] = mn[w];
        }
        #pragma unroll
        for (int nt = 0; nt < 8; nt++) {
            o[nt][0] *= f[0]; o[nt][1] *= f[0];
            o[nt][2] *= f[1]; o[nt][3] *= f[1];
        }

        // P fragments from S accumulators (layout identity)
        uint32_t pf[4][4];
        #pragma unroll
        for (int ks = 0; ks < 4; ks++) {
            pf[ks][0] = pack_bf16x2(s[2 * ks][0],     s[2 * ks][1]);
            pf[ks][1] = pack_bf16x2(s[2 * ks][2],     s[2 * ks][3]);
            pf[ks][2] = pack_bf16x2(s[2 * ks + 1][0], s[2 * ks + 1][1]);
            pf[ks][3] = pack_bf16x2(s[2 * ks + 1][2], s[2 * ks + 1][3]);
        }

        // O += P @ V
        #pragma unroll
        for (int ks = 0; ks < 4; ks++) {
            #pragma unroll
            for (int tp = 0; tp < 4; tp++) {
                uint32_t vf[4];
                ldsm_x4_t(vf, vst + (ks * 16 + vrow) * 144 + (tp * 16 + vcol) * 2);
                mma16816(o[2 * tp],     pf[ks], vf[0], vf[1]);
                mma16816(o[2 * tp + 1], pf[ks], vf[2], vf[3]);
            }
        }
        __syncthreads();
    }

    // finalize: /l, *0.9, + residual x
    const float inv0 = 1.0f / lrow[0];
    const float inv1 = 1.0f / lrow[1];
    const int r0 = q0 + wid * 16 + (lane >> 2);
    const size_t row0 = ((size_t)b * P_ + r0) * D_ + hc + (lane & 3) * 2;
    const size_t row1 = row0 + 8 * D_;
    #pragma unroll
    for (int nt = 0; nt < 8; nt++) {
        float2 xa = *(const float2*)&x[row0 + nt * 8];
        float2 ra;
        ra.x = o[nt][0] * inv0 * SURV_ + xa.x;
        ra.y = o[nt][1] * inv0 * SURV_ + xa.y;
        *(float2*)&x1[row0 + nt * 8] = ra;
        float2 xb = *(const float2*)&x[row1 + nt * 8];
        float2 rb;
        rb.x = o[nt][2] * inv1 * SURV_ + xb.x;
        rb.y = o[nt][3] * inv1 * SURV_ + xb.y;
        *(float2*)&x1[row1 + nt * 8] = rb;
    }
}

// ---------------- launch ----------------------------------------------------
extern "C" void kernel_launch(void* const* d_in, const int* in_sizes, int n_in,
                              void* d_out, int out_size)
{
    const float* x     = (const float*)d_in[0];
    const float* ln1_g = (const float*)d_in[1];
    const float* ln1_b = (const float*)d_in[2];
    const float* w_qkv = (const float*)d_in[3];
    const float* b_qkv = (const float*)d_in[4];
    const float* ln2_g = (const float*)d_in[5];
    const float* ln2_b = (const float*)d_in[6];
    const float* w1    = (const float*)d_in[7];
    const float* b1    = (const float*)d_in[8];
    const float* w2    = (const float*)d_in[9];
    const float* b2    = (const float*)d_in[10];
    float* out = (float*)d_out;

    __nv_bfloat16 *h_hi, *h_lo, *qkvb, *ffn_hi, *ffn_lo;
    __nv_bfloat16 *wq_hi, *wq_lo, *w1_hi, *w1_lo, *w2_hi, *w2_lo;
    float *x1;
    cudaGetSymbolAddress((void**)&h_hi,   g_h_hi);
    cudaGetSymbolAddress((void**)&h_lo,   g_h_lo);
    cudaGetSymbolAddress((void**)&qkvb,   g_qkvb);
    cudaGetSymbolAddress((void**)&x1,     g_x1);
    cudaGetSymbolAddress((void**)&ffn_hi, g_ffn_hi);
    cudaGetSymbolAddress((void**)&ffn_lo, g_ffn_lo);
    cudaGetSymbolAddress((void**)&wq_hi,  g_wq_hi);
    cudaGetSymbolAddress((void**)&wq_lo,  g_wq_lo);
    cudaGetSymbolAddress((void**)&w1_hi,  g_w1_hi);
    cudaGetSymbolAddress((void**)&w1_lo,  g_w1_lo);
    cudaGetSymbolAddress((void**)&w2_hi,  g_w2_hi);
    cudaGetSymbolAddress((void**)&w2_lo,  g_w2_lo);

    cudaFuncSetAttribute(gemm_mma<1>,
                         cudaFuncAttributeMaxDynamicSharedMemorySize, GEMM_SMEM);
    cudaFuncSetAttribute(gemm_mma<2>,
                         cudaFuncAttributeMaxDynamicSharedMemorySize, GEMM_SMEM);
    cudaFuncSetAttribute(gemm_mma<3>,
                         cudaFuncAttributeMaxDynamicSharedMemorySize, GEMM_SMEM);
    cudaFuncSetAttribute(flash_mma,
                         cudaFuncAttributeMaxDynamicSharedMemorySize, FLASH_SMEM);

    // weight transpose + split
    wsplit_kernel<<<dim3(D3_ / 32, D_ / 32), 256>>>(w_qkv, wq_hi, wq_lo, D_, D3_);
    wsplit_kernel<<<dim3(DFF_ / 32, D_ / 32), 256>>>(w1, w1_hi, w1_lo, D_, DFF_);
    wsplit_kernel<<<dim3(D_ / 32, DFF_ / 32), 256>>>(w2, w2_hi, w2_lo, DFF_, D_);

    // 1) LN1 -> split bf16
    ln_split_kernel<<<NTOK / 8, 256>>>(x, ln1_g, ln1_b, h_hi, h_lo);
    // 2) QKV projection -> bf16
    gemm_mma<3><<<dim3(D3_ / BN, NTOK / BM), 256, GEMM_SMEM>>>(
        h_hi, h_lo, wq_hi, wq_lo, b_qkv, nullptr,
        nullptr, qkvb, nullptr, NTOK, D3_, D_);
    // 3) attention + residual -> x1
    flash_mma<<<dim3(P_ / FQT, H_, B_), 128, FLASH_SMEM>>>(qkvb, x, x1);
    // 4) LN2 -> split bf16
    ln_split_kernel<<<NTOK / 8, 256>>>(x1, ln2_g, ln2_b, h_hi, h_lo);
    // 5) MLP up + GELU -> split bf16
    gemm_mma<1><<<dim3(DFF_ / BN, NTOK / BM), 256, GEMM_SMEM>>>(
        h_hi, h_lo, w1_hi, w1_lo, b1, nullptr,
        nullptr, ffn_hi, ffn_lo, NTOK, DFF_, D_);
    // 6) MLP down + droppath + residual -> out
    gemm_mma<2><<<dim3(D_ / BN, NTOK / BM), 256, GEMM_SMEM>>>(
        ffn_hi, ffn_lo, w2_hi, w2_lo, b2, x1,
        out, nullptr, nullptr, NTOK, D_, DFF_);
}

// round 7
// speedup vs baseline: 1.5279x; 1.3294x over previous
#include <cuda_runtime.h>
#include <cuda_fp16.h>
#include <math.h>
#include <stdint.h>

#define D_    768
#define P_    2048
#define B_    4
#define H_    12
#define DFF_  3072
#define NTOK  (B_ * P_)      /* 8192 */
#define D3_   (3 * D_)       /* 2304 */
#define EPS_  1e-3f
#define SURV_ 0.9f

// ---------------- scratch (static device globals) ---------------------------
__device__ __half g_h   [NTOK * D_];     // LN output, fp16
__device__ __half g_qkvh[NTOK * D3_];    // fp16 QKV
__device__ float  g_x1  [NTOK * D_];
__device__ __half g_ffn [NTOK * DFF_];   // MLP hidden, fp16
// transposed+split weights: [N, K] layout, fp16 hi/lo
__device__ __half g_wq_hi[D3_ * D_],  g_wq_lo[D3_ * D_];
__device__ __half g_w1_hi[DFF_ * D_], g_w1_lo[DFF_ * D_];
__device__ __half g_w2_hi[D_ * DFF_], g_w2_lo[D_ * DFF_];

// ---------------- helpers ----------------------------------------------------
__device__ __forceinline__ uint32_t smem_u32(const void* p) {
    uint32_t a;
    asm("{ .reg .u64 t; cvta.to.shared.u64 t, %1; cvt.u32.u64 %0, t; }"
        : "=r"(a) : "l"(p));
    return a;
}
__device__ __forceinline__ void ldsm_x4(uint32_t* r, uint32_t addr) {
    asm volatile("ldmatrix.sync.aligned.m8n8.x4.shared.b16 {%0,%1,%2,%3}, [%4];"
                 : "=r"(r[0]), "=r"(r[1]), "=r"(r[2]), "=r"(r[3]) : "r"(addr));
}
__device__ __forceinline__ void ldsm_x4_t(uint32_t* r, uint32_t addr) {
    asm volatile("ldmatrix.sync.aligned.m8n8.x4.trans.shared.b16 {%0,%1,%2,%3}, [%4];"
                 : "=r"(r[0]), "=r"(r[1]), "=r"(r[2]), "=r"(r[3]) : "r"(addr));
}
__device__ __forceinline__ void mma16816(float* c, const uint32_t* a,
                                         uint32_t b0, uint32_t b1) {
    asm volatile(
        "mma.sync.aligned.m16n8k16.row.col.f32.f16.f16.f32 "
        "{%0,%1,%2,%3}, {%4,%5,%6,%7}, {%8,%9}, {%0,%1,%2,%3};"
        : "+f"(c[0]), "+f"(c[1]), "+f"(c[2]), "+f"(c[3])
        : "r"(a[0]), "r"(a[1]), "r"(a[2]), "r"(a[3]), "r"(b0), "r"(b1));
}
__device__ __forceinline__ float ex2f(float x) {
    float y; asm("ex2.approx.f32 %0, %1;" : "=f"(y) : "f"(x)); return y;
}
// packed fp16x2 = {hi:hi_f, lo:lo_f}
__device__ __forceinline__ uint32_t pack_f16x2(float lo, float hi) {
    uint32_t d;
    asm("cvt.rn.f16x2.f32 %0, %1, %2;" : "=r"(d) : "f"(hi), "f"(lo));
    return d;
}
__device__ __forceinline__ void cp_async16(uint32_t dst, const void* src) {
    asm volatile("cp.async.cg.shared.global [%0], [%1], 16;"
                 :: "r"(dst), "l"(src));
}
#define CP_COMMIT() asm volatile("cp.async.commit_group;" ::: "memory")
#define CP_WAIT(n)  asm volatile("cp.async.wait_group %0;" :: "n"(n) : "memory")

// ---------------- LayerNorm -> fp16 (warp-per-row) ---------------------------
__global__ void __launch_bounds__(256) ln_f16_kernel(
    const float* __restrict__ x, const float* __restrict__ g,
    const float* __restrict__ b, __half* __restrict__ out)
{
    const int row  = blockIdx.x * 8 + (threadIdx.x >> 5);
    const int lane = threadIdx.x & 31;
    const float4* xr = (const float4*)(x + (size_t)row * D_);
    const float4* gv = (const float4*)g;
    const float4* bv = (const float4*)b;

    float4 v[6];
    float s = 0.f;
    #pragma unroll
    for (int k = 0; k < 6; k++) {
        v[k] = xr[lane + 32 * k];
        s += v[k].x + v[k].y + v[k].z + v[k].w;
    }
    #pragma unroll
    for (int o = 16; o; o >>= 1) s += __shfl_xor_sync(0xffffffffu, s, o);
    const float mu = s * (1.0f / D_);

    float q = 0.f;
    #pragma unroll
    for (int k = 0; k < 6; k++) {
        v[k].x -= mu; v[k].y -= mu; v[k].z -= mu; v[k].w -= mu;
        q += v[k].x * v[k].x + v[k].y * v[k].y + v[k].z * v[k].z + v[k].w * v[k].w;
    }
    #pragma unroll
    for (int o = 16; o; o >>= 1) q += __shfl_xor_sync(0xffffffffu, q, o);
    const float rs = rsqrtf(q * (1.0f / D_) + EPS_);

    uint2* hp = (uint2*)(out + (size_t)row * D_);
    #pragma unroll
    for (int k = 0; k < 6; k++) {
        const int i4 = lane + 32 * k;
        float4 gg = gv[i4], bb = bv[i4];
        float o0 = v[k].x * rs * gg.x + bb.x;
        float o1 = v[k].y * rs * gg.y + bb.y;
        float o2 = v[k].z * rs * gg.z + bb.z;
        float o3 = v[k].w * rs * gg.w + bb.w;
        hp[i4] = make_uint2(pack_f16x2(o0, o1), pack_f16x2(o2, o3));
    }
}

// ---------------- weight transpose + split: w[K,N] -> wt_{hi,lo}[N,K] -------
__global__ void __launch_bounds__(256) wsplit_kernel(
    const float* __restrict__ w, __half* __restrict__ hi,
    __half* __restrict__ lo, int K, int N)
{
    __shared__ float t[32][33];
    const int n0 = blockIdx.x * 32, k0 = blockIdx.y * 32;
    const int tx = threadIdx.x & 31, ty = threadIdx.x >> 5;
    #pragma unroll
    for (int j = 0; j < 4; j++) {
        int k = ty + j * 8;
        t[k][tx] = w[(size_t)(k0 + k) * N + n0 + tx];
    }
    __syncthreads();
    #pragma unroll
    for (int j = 0; j < 4; j++) {
        int n = ty + j * 8;
        float v = t[tx][n];
        __half h = __float2half(v);
        size_t o = (size_t)(n0 + n) * K + k0 + tx;
        hi[o] = h;
        lo[o] = __float2half(v - __half2float(h));
    }
}

// ---------------- MMA GEMM: C[M,N] = A[M,K] @ (Bhi+Blo)[N,K]^T ---------------
// fp16 A (single), fp16 split B. 128x128 tile, K chunk 32, 2 MMA passes.
// 8 warps (4m x 2n), warp = 32x64. 2 CTAs/SM, cp.async 2-stage.
// EPI: 1 bias+GELU->fp16 ; 2 bias,*0.9+res->fp32 ; 3 bias->fp16
#define BM   128
#define BN   128
#define BKC  32
#define TILEB 10240       /* 128 * 80 bytes */
#define STAGEB 30720      /* A + Bhi + Blo */
#define GEMM_SMEM (2 * STAGEB)

template <int EPI>
__global__ void __launch_bounds__(256, 2) gemm_mma(
    const __half* __restrict__ A_g,
    const __half* __restrict__ Bhi_g, const __half* __restrict__ Blo_g,
    const float* __restrict__ bias, const float* __restrict__ res,
    float* __restrict__ Cf, __half* __restrict__ Ch,
    int M, int N, int K)
{
    extern __shared__ char dsm[];
    const uint32_t sbase = smem_u32(dsm);

    const int tid  = threadIdx.x;
    const int lane = tid & 31;
    const int wid  = tid >> 5;
    const int wm   = wid & 3;
    const int wn   = wid >> 2;
    const int m0   = blockIdx.y * BM;
    const int n0   = blockIdx.x * BN;

    const int a_row = lane & 15;
    const int a_col = (lane >> 4) << 3;
    const uint32_t offA = (uint32_t)((wm * 32 + a_row) * 80 + a_col * 2);
    const int b_row = (lane & 7) | ((lane >> 4) << 3);
    const int b_col = ((lane >> 3) & 1) << 3;
    const uint32_t offB = (uint32_t)(TILEB + (wn * 64 + b_row) * 80 + b_col * 2);

    float acc[2][8][4];
    #pragma unroll
    for (int i = 0; i < 2; i++)
        #pragma unroll
        for (int j = 0; j < 8; j++)
            #pragma unroll
            for (int k = 0; k < 4; k++) acc[i][j][k] = 0.f;

    const int ldu = K >> 3;
    const uint4* ga  = (const uint4*)A_g;
    const uint4* gbh = (const uint4*)Bhi_g;
    const uint4* gbl = (const uint4*)Blo_g;

    const int r_0 = tid >> 2,         q_0 = tid & 3;
    const int r_1 = (tid + 256) >> 2, q_1 = (tid + 256) & 3;

    const int nchunks = K / BKC;

    auto issue = [&](int stage, int ch) {
        const int k0u = ch * (BKC / 8);
        const uint32_t so = sbase + (uint32_t)stage * STAGEB;
        {
            uint32_t d = so + (uint32_t)(r_0 * 80 + q_0 * 16);
            cp_async16(d,             ga  + (size_t)(m0 + r_0) * ldu + k0u + q_0);
            cp_async16(d + TILEB,     gbh + (size_t)(n0 + r_0) * ldu + k0u + q_0);
            cp_async16(d + 2 * TILEB, gbl + (size_t)(n0 + r_0) * ldu + k0u + q_0);
        }
        {
            uint32_t d = so + (uint32_t)(r_1 * 80 + q_1 * 16);
            cp_async16(d,             ga  + (size_t)(m0 + r_1) * ldu + k0u + q_1);
            cp_async16(d + TILEB,     gbh + (size_t)(n0 + r_1) * ldu + k0u + q_1);
            cp_async16(d + 2 * TILEB, gbl + (size_t)(n0 + r_1) * ldu + k0u + q_1);
        }
    };

    issue(0, 0);
    CP_COMMIT();

    for (int ch = 0; ch < nchunks; ch++) {
        if (ch + 1 < nchunks) {
            issue((ch + 1) & 1, ch + 1);
            CP_COMMIT();
            CP_WAIT(1);
        } else {
            CP_WAIT(0);
        }
        __syncthreads();

        const uint32_t st = sbase + (uint32_t)(ch & 1) * STAGEB;
        const uint32_t aT  = st + offA;
        const uint32_t bHi = st + offB;
        const uint32_t bLo = bHi + TILEB;

        #pragma unroll
        for (int ks = 0; ks < BKC; ks += 16) {
            uint32_t ah[2][4];
            #pragma unroll
            for (int mt = 0; mt < 2; mt++)
                ldsm_x4(ah[mt], aT + mt * 1280 + ks * 2);
            #pragma unroll
            for (int np = 0; np < 4; np++) {
                uint32_t bh[4], bl[4];
                ldsm_x4(bh, bHi + np * 1280 + ks * 2);
                ldsm_x4(bl, bLo + np * 1280 + ks * 2);
                #pragma unroll
                for (int mt = 0; mt < 2; mt++) {
                    mma16816(acc[mt][2 * np],     ah[mt], bh[0], bh[1]);
                    mma16816(acc[mt][2 * np + 1], ah[mt], bh[2], bh[3]);
                    mma16816(acc[mt][2 * np],     ah[mt], bl[0], bl[1]);
                    mma16816(acc[mt][2 * np + 1], ah[mt], bl[2], bl[3]);
                }
            }
        }
        __syncthreads();
    }

    // epilogue
    const int lr = lane >> 2;
    const int lc = (lane & 3) * 2;
    #pragma unroll
    for (int mt = 0; mt < 2; mt++) {
        #pragma unroll
        for (int nt = 0; nt < 8; nt++) {
            #pragma unroll
            for (int hh = 0; hh < 2; hh++) {
                const int gr = m0 + wm * 32 + mt * 16 + lr + hh * 8;
                const int gc = n0 + wn * 64 + nt * 8 + lc;
                float v0 = acc[mt][nt][hh * 2 + 0] + bias[gc];
                float v1 = acc[mt][nt][hh * 2 + 1] + bias[gc + 1];
                const size_t go = (size_t)gr * N + gc;
                if (EPI == 1) {
                    v0 = 0.5f * v0 * (1.0f + erff(v0 * 0.70710678118654752f));
                    v1 = 0.5f * v1 * (1.0f + erff(v1 * 0.70710678118654752f));
                    ((uint32_t*)Ch)[go >> 1] = pack_f16x2(v0, v1);
                } else if (EPI == 2) {
                    float2 rr = *(const float2*)&res[go];
                    float2 o2 = make_float2(v0 * SURV_ + rr.x, v1 * SURV_ + rr.y);
                    *(float2*)&Cf[go] = o2;
                } else {  // EPI == 3
                    ((uint32_t*)Ch)[go >> 1] = pack_f16x2(v0, v1);
                }
            }
        }
    }
}

// ---------------- Flash attention (fp16 MMA, q-tile 64, cp.async K/V) -------
// One CTA per (q_tile 64, head, batch); 128 threads (4 warps, 16 q-rows each).
#define FQT 64
#define KT  64
#define QB_  9216                  /* 64 rows * 144B */
#define KB_  9216
#define FLASH_SMEM (QB_ + 4 * KB_) /* Q + 2-stage K + 2-stage V = 46080 */

__global__ void __launch_bounds__(128) flash_mma(
    const __half* __restrict__ qkv, const float* __restrict__ x,
    float* __restrict__ x1)
{
    extern __shared__ char fsm[];
    const uint32_t sb = smem_u32(fsm);

    const int t = threadIdx.x;
    const int lane = t & 31, wid = t >> 5;
    const int qt = blockIdx.x, h = blockIdx.y, b = blockIdx.z;
    const size_t base = (size_t)b * P_ * D3_;
    const int q0 = qt * FQT, hc = h * 64;

    // load Q tile (64x64 fp16)
    #pragma unroll
    for (int i = 0; i < 4; i++) {
        int idx = t + i * 128;
        int r = idx >> 3, c8 = (idx & 7) << 3;
        *(uint4*)(fsm + r * 144 + c8 * 2) =
            *(const uint4*)(qkv + base + (size_t)(q0 + r) * D3_ + hc + c8);
    }

    auto issueKV = [&](int stage, int kt) {
        const int k0 = kt * KT;
        const uint32_t kb = sb + QB_ + (uint32_t)stage * KB_;
        const uint32_t vb = sb + QB_ + 2 * KB_ + (uint32_t)stage * KB_;
        #pragma unroll
        for (int i = 0; i < 4; i++) {
            int idx = t + i * 128;
            int r = idx >> 3, c8 = (idx & 7) << 3;
            cp_async16(kb + r * 144 + c8 * 2,
                       qkv + base + (size_t)(k0 + r) * D3_ + D_ + hc + c8);
            cp_async16(vb + r * 144 + c8 * 2,
                       qkv + base + (size_t)(k0 + r) * D3_ + 2 * D_ + hc + c8);
        }
    };

    issueKV(0, 0);
    CP_COMMIT();
    __syncthreads();

    // preload Q fragments (constant across kt)
    uint32_t qf[4][4];
    {
        const int qrow = wid * 16 + (lane & 15);
        const int qc = (lane >> 4) << 3;
        #pragma unroll
        for (int ks = 0; ks < 4; ks++)
            ldsm_x4(qf[ks], sb + qrow * 144 + (ks * 16 + qc) * 2);
    }

    float mrow[2] = {-1e30f, -1e30f};
    float lrow[2] = {0.f, 0.f};
    float o[8][4];
    #pragma unroll
    for (int i = 0; i < 8; i++)
        #pragma unroll
        for (int j = 0; j < 4; j++) o[i][j] = 0.f;

    const float SCL = 0.18033688011112042f;  // (1/8) * log2(e)

    const int krow = (lane & 7) + ((lane >> 4) << 3);
    const int kcol = ((lane >> 3) & 1) << 3;
    const int vrow = (lane & 7) + (((lane >> 3) & 1) << 3);
    const int vcol = (lane >> 4) << 3;

    const int niter = P_ / KT;
    for (int kt = 0; kt < niter; kt++) {
        if (kt + 1 < niter) {
            issueKV((kt + 1) & 1, kt + 1);
            CP_COMMIT();
            CP_WAIT(1);
        } else {
            CP_WAIT(0);
        }
        __syncthreads();

        const uint32_t kst = sb + QB_ + (uint32_t)(kt & 1) * KB_;
        const uint32_t vst = sb + QB_ + 2 * KB_ + (uint32_t)(kt & 1) * KB_;

        // S = Q @ K^T
        float s[8][4];
        #pragma unroll
        for (int i = 0; i < 8; i++)
            #pragma unroll
            for (int j = 0; j < 4; j++) s[i][j] = 0.f;
        #pragma unroll
        for (int ks = 0; ks < 4; ks++) {
            #pragma unroll
            for (int tp = 0; tp < 4; tp++) {
                uint32_t kf[4];
                ldsm_x4(kf, kst + (tp * 16 + krow) * 144 + (ks * 16 + kcol) * 2);
                mma16816(s[2 * tp],     qf[ks], kf[0], kf[1]);
                mma16816(s[2 * tp + 1], qf[ks], kf[2], kf[3]);
            }
        }

        // online softmax
        float pm[2] = {-1e30f, -1e30f};
        #pragma unroll
        for (int nt = 0; nt < 8; nt++) {
            pm[0] = fmaxf(pm[0], fmaxf(s[nt][0], s[nt][1]));
            pm[1] = fmaxf(pm[1], fmaxf(s[nt][2], s[nt][3]));
        }
        #pragma unroll
        for (int w = 0; w < 2; w++) {
            pm[w] = fmaxf(pm[w], __shfl_xor_sync(0xffffffffu, pm[w], 1));
            pm[w] = fmaxf(pm[w], __shfl_xor_sync(0xffffffffu, pm[w], 2));
        }
        float mn[2], f[2], sum[2];
        #pragma unroll
        for (int w = 0; w < 2; w++) {
            mn[w] = fmaxf(mrow[w], pm[w]);
            f[w]  = ex2f((mrow[w] - mn[w]) * SCL);
            sum[w] = 0.f;
        }
        #pragma unroll
        for (int nt = 0; nt < 8; nt++) {
            s[nt][0] = ex2f((s[nt][0] - mn[0]) * SCL);
            s[nt][1] = ex2f((s[nt][1] - mn[0]) * SCL);
            s[nt][2] = ex2f((s[nt][2] - mn[1]) * SCL);
            s[nt][3] = ex2f((s[nt][3] - mn[1]) * SCL);
            sum[0] += s[nt][0] + s[nt][1];
            sum[1] += s[nt][2] + s[nt][3];
        }
        #pragma unroll
        for (int w = 0; w < 2; w++) {
            sum[w] += __shfl_xor_sync(0xffffffffu, sum[w], 1);
            sum[w] += __shfl_xor_sync(0xffffffffu, sum[w], 2);
            lrow[w] = lrow[w] * f[w] + sum[w];
            mrow[w] = mn[w];
        }
        #pragma unroll
        for (int nt = 0; nt < 8; nt++) {
            o[nt][0] *= f[0]; o[nt][1] *= f[0];
            o[nt][2] *= f[1]; o[nt][3] *= f[1];
        }

        // P fragments (fp16) from S accumulators (layout identity)
        uint32_t pf[4][4];
        #pragma unroll
        for (int ks = 0; ks < 4; ks++) {
            pf[ks][0] = pack_f16x2(s[2 * ks][0],     s[2 * ks][1]);
            pf[ks][1] = pack_f16x2(s[2 * ks][2],     s[2 * ks][3]);
            pf[ks][2] = pack_f16x2(s[2 * ks + 1][0], s[2 * ks + 1][1]);
            pf[ks][3] = pack_f16x2(s[2 * ks + 1][2], s[2 * ks + 1][3]);
        }

        // O += P @ V
        #pragma unroll
        for (int ks = 0; ks < 4; ks++) {
            #pragma unroll
            for (int tp = 0; tp < 4; tp++) {
                uint32_t vf[4];
                ldsm_x4_t(vf, vst + (ks * 16 + vrow) * 144 + (tp * 16 + vcol) * 2);
                mma16816(o[2 * tp],     pf[ks], vf[0], vf[1]);
                mma16816(o[2 * tp + 1], pf[ks], vf[2], vf[3]);
            }
        }
        __syncthreads();
    }

    // finalize: /l, *0.9, + residual x
    const float inv0 = 1.0f / lrow[0];
    const float inv1 = 1.0f / lrow[1];
    const int r0 = q0 + wid * 16 + (lane >> 2);
    const size_t row0 = ((size_t)b * P_ + r0) * D_ + hc + (lane & 3) * 2;
    const size_t row1 = row0 + 8 * D_;
    #pragma unroll
    for (int nt = 0; nt < 8; nt++) {
        float2 xa = *(const float2*)&x[row0 + nt * 8];
        float2 ra;
        ra.x = o[nt][0] * inv0 * SURV_ + xa.x;
        ra.y = o[nt][1] * inv0 * SURV_ + xa.y;
        *(float2*)&x1[row0 + nt * 8] = ra;
        float2 xb = *(const float2*)&x[row1 + nt * 8];
        float2 rb;
        rb.x = o[nt][2] * inv1 * SURV_ + xb.x;
        rb.y = o[nt][3] * inv1 * SURV_ + xb.y;
        *(float2*)&x1[row1 + nt * 8] = rb;
    }
}

// ---------------- launch ----------------------------------------------------
extern "C" void kernel_launch(void* const* d_in, const int* in_sizes, int n_in,
                              void* d_out, int out_size)
{
    const float* x     = (const float*)d_in[0];
    const float* ln1_g = (const float*)d_in[1];
    const float* ln1_b = (const float*)d_in[2];
    const float* w_qkv = (const float*)d_in[3];
    const float* b_qkv = (const float*)d_in[4];
    const float* ln2_g = (const float*)d_in[5];
    const float* ln2_b = (const float*)d_in[6];
    const float* w1    = (const float*)d_in[7];
    const float* b1    = (const float*)d_in[8];
    const float* w2    = (const float*)d_in[9];
    const float* b2    = (const float*)d_in[10];
    float* out = (float*)d_out;

    __half *h, *qkvh, *ffn;
    __half *wq_hi, *wq_lo, *w1_hi, *w1_lo, *w2_hi, *w2_lo;
    float *x1;
    cudaGetSymbolAddress((void**)&h,     g_h);
    cudaGetSymbolAddress((void**)&qkvh,  g_qkvh);
    cudaGetSymbolAddress((void**)&x1,    g_x1);
    cudaGetSymbolAddress((void**)&ffn,   g_ffn);
    cudaGetSymbolAddress((void**)&wq_hi, g_wq_hi);
    cudaGetSymbolAddress((void**)&wq_lo, g_wq_lo);
    cudaGetSymbolAddress((void**)&w1_hi, g_w1_hi);
    cudaGetSymbolAddress((void**)&w1_lo, g_w1_lo);
    cudaGetSymbolAddress((void**)&w2_hi, g_w2_hi);
    cudaGetSymbolAddress((void**)&w2_lo, g_w2_lo);

    cudaFuncSetAttribute(gemm_mma<1>,
                         cudaFuncAttributeMaxDynamicSharedMemorySize, GEMM_SMEM);
    cudaFuncSetAttribute(gemm_mma<2>,
                         cudaFuncAttributeMaxDynamicSharedMemorySize, GEMM_SMEM);
    cudaFuncSetAttribute(gemm_mma<3>,
                         cudaFuncAttributeMaxDynamicSharedMemorySize, GEMM_SMEM);
    cudaFuncSetAttribute(flash_mma,
                         cudaFuncAttributeMaxDynamicSharedMemorySize, FLASH_SMEM);

    // weight transpose + split (fp16 hi/lo)
    wsplit_kernel<<<dim3(D3_ / 32, D_ / 32), 256>>>(w_qkv, wq_hi, wq_lo, D_, D3_);
    wsplit_kernel<<<dim3(DFF_ / 32, D_ / 32), 256>>>(w1, w1_hi, w1_lo, D_, DFF_);
    wsplit_kernel<<<dim3(D_ / 32, DFF_ / 32), 256>>>(w2, w2_hi, w2_lo, DFF_, D_);

    // 1) LN1 -> fp16
    ln_f16_kernel<<<NTOK / 8, 256>>>(x, ln1_g, ln1_b, h);
    // 2) QKV projection -> fp16
    gemm_mma<3><<<dim3(D3_ / BN, NTOK / BM), 256, GEMM_SMEM>>>(
        h, wq_hi, wq_lo, b_qkv, nullptr,
        nullptr, qkvh, NTOK, D3_, D_);
    // 3) attention + residual -> x1
    flash_mma<<<dim3(P_ / FQT, H_, B_), 128, FLASH_SMEM>>>(qkvh, x, x1);
    // 4) LN2 -> fp16
    ln_f16_kernel<<<NTOK / 8, 256>>>(x1, ln2_g, ln2_b, h);
    // 5) MLP up + GELU -> fp16
    gemm_mma<1><<<dim3(DFF_ / BN, NTOK / BM), 256, GEMM_SMEM>>>(
        h, w1_hi, w1_lo, b1, nullptr,
        nullptr, ffn, NTOK, DFF_, D_);
    // 6) MLP down + droppath + residual -> out
    gemm_mma<2><<<dim3(D_ / BN, NTOK / BM), 256, GEMM_SMEM>>>(
        ffn, w2_hi, w2_lo, b2, x1,
        out, nullptr, NTOK, D_, DFF_);
}

// round 8
// speedup vs baseline: 2.3484x; 1.5369x over previous
#include <cuda_runtime.h>
#include <cuda_fp16.h>
#include <math.h>
#include <stdint.h>

#define D_    768
#define P_    2048
#define B_    4
#define H_    12
#define DFF_  3072
#define NTOK  (B_ * P_)      /* 8192 */
#define D3_   (3 * D_)       /* 2304 */
#define EPS_  1e-3f
#define SURV_ 0.9f

// ---------------- scratch (static device globals) ---------------------------
__device__ __half g_h   [NTOK * D_];     // LN output, fp16
__device__ __half g_qkvh[NTOK * D3_];    // fp16 QKV
__device__ float  g_x1  [NTOK * D_];
__device__ __half g_ffn [NTOK * DFF_];   // MLP hidden, fp16
// transposed weights: [N, K] layout, fp16
__device__ __half g_wq[D3_ * D_];
__device__ __half g_w1[DFF_ * D_];
__device__ __half g_w2[D_ * DFF_];

// ---------------- helpers ----------------------------------------------------
__device__ __forceinline__ uint32_t smem_u32(const void* p) {
    uint32_t a;
    asm("{ .reg .u64 t; cvta.to.shared.u64 t, %1; cvt.u32.u64 %0, t; }"
        : "=r"(a) : "l"(p));
    return a;
}
__device__ __forceinline__ void ldsm_x4(uint32_t* r, uint32_t addr) {
    asm volatile("ldmatrix.sync.aligned.m8n8.x4.shared.b16 {%0,%1,%2,%3}, [%4];"
                 : "=r"(r[0]), "=r"(r[1]), "=r"(r[2]), "=r"(r[3]) : "r"(addr));
}
__device__ __forceinline__ void ldsm_x4_t(uint32_t* r, uint32_t addr) {
    asm volatile("ldmatrix.sync.aligned.m8n8.x4.trans.shared.b16 {%0,%1,%2,%3}, [%4];"
                 : "=r"(r[0]), "=r"(r[1]), "=r"(r[2]), "=r"(r[3]) : "r"(addr));
}
__device__ __forceinline__ void mma16816(float* c, const uint32_t* a,
                                         uint32_t b0, uint32_t b1) {
    asm volatile(
        "mma.sync.aligned.m16n8k16.row.col.f32.f16.f16.f32 "
        "{%0,%1,%2,%3}, {%4,%5,%6,%7}, {%8,%9}, {%0,%1,%2,%3};"
        : "+f"(c[0]), "+f"(c[1]), "+f"(c[2]), "+f"(c[3])
        : "r"(a[0]), "r"(a[1]), "r"(a[2]), "r"(a[3]), "r"(b0), "r"(b1));
}
__device__ __forceinline__ float ex2f(float x) {
    float y; asm("ex2.approx.f32 %0, %1;" : "=f"(y) : "f"(x)); return y;
}
// packed fp16x2 = {hi:hi_f, lo:lo_f}
__device__ __forceinline__ uint32_t pack_f16x2(float lo, float hi) {
    uint32_t d;
    asm("cvt.rn.f16x2.f32 %0, %1, %2;" : "=r"(d) : "f"(hi), "f"(lo));
    return d;
}
__device__ __forceinline__ void cp_async16(uint32_t dst, const void* src) {
    asm volatile("cp.async.cg.shared.global [%0], [%1], 16;"
                 :: "r"(dst), "l"(src));
}
#define CP_COMMIT() asm volatile("cp.async.commit_group;" ::: "memory")
#define CP_WAIT(n)  asm volatile("cp.async.wait_group %0;" :: "n"(n) : "memory")

// ---------------- LayerNorm -> fp16 (warp-per-row) ---------------------------
__global__ void __launch_bounds__(256) ln_f16_kernel(
    const float* __restrict__ x, const float* __restrict__ g,
    const float* __restrict__ b, __half* __restrict__ out)
{
    const int row  = blockIdx.x * 8 + (threadIdx.x >> 5);
    const int lane = threadIdx.x & 31;
    const float4* xr = (const float4*)(x + (size_t)row * D_);
    const float4* gv = (const float4*)g;
    const float4* bv = (const float4*)b;

    float4 v[6];
    float s = 0.f;
    #pragma unroll
    for (int k = 0; k < 6; k++) {
        v[k] = xr[lane + 32 * k];
        s += v[k].x + v[k].y + v[k].z + v[k].w;
    }
    #pragma unroll
    for (int o = 16; o; o >>= 1) s += __shfl_xor_sync(0xffffffffu, s, o);
    const float mu = s * (1.0f / D_);

    float q = 0.f;
    #pragma unroll
    for (int k = 0; k < 6; k++) {
        v[k].x -= mu; v[k].y -= mu; v[k].z -= mu; v[k].w -= mu;
        q += v[k].x * v[k].x + v[k].y * v[k].y + v[k].z * v[k].z + v[k].w * v[k].w;
    }
    #pragma unroll
    for (int o = 16; o; o >>= 1) q += __shfl_xor_sync(0xffffffffu, q, o);
    const float rs = rsqrtf(q * (1.0f / D_) + EPS_);

    uint2* hp = (uint2*)(out + (size_t)row * D_);
    #pragma unroll
    for (int k = 0; k < 6; k++) {
        const int i4 = lane + 32 * k;
        float4 gg = gv[i4], bb = bv[i4];
        float o0 = v[k].x * rs * gg.x + bb.x;
        float o1 = v[k].y * rs * gg.y + bb.y;
        float o2 = v[k].z * rs * gg.z + bb.z;
        float o3 = v[k].w * rs * gg.w + bb.w;
        hp[i4] = make_uint2(pack_f16x2(o0, o1), pack_f16x2(o2, o3));
    }
}

// ---------------- weight transpose + cast: w[K,N] -> wt[N,K] fp16 -----------
__global__ void __launch_bounds__(256) wcast_kernel(
    const float* __restrict__ w, __half* __restrict__ wt, int K, int N)
{
    __shared__ float t[32][33];
    const int n0 = blockIdx.x * 32, k0 = blockIdx.y * 32;
    const int tx = threadIdx.x & 31, ty = threadIdx.x >> 5;
    #pragma unroll
    for (int j = 0; j < 4; j++) {
        int k = ty + j * 8;
        t[k][tx] = w[(size_t)(k0 + k) * N + n0 + tx];
    }
    __syncthreads();
    #pragma unroll
    for (int j = 0; j < 4; j++) {
        int n = ty + j * 8;
        wt[(size_t)(n0 + n) * K + k0 + tx] = __float2half(t[tx][n]);
    }
}

// ---------------- MMA GEMM: C[M,N] = A[M,K] @ B[N,K]^T, fp16 single-pass ----
// 128x128 tile, K chunk 64, 256 threads, 8 warps (4m x 2n), warp 32x64.
// cp.async 2-stage, 2 CTAs/SM.
// EPI: 1 bias+GELU->fp16 ; 2 bias,*0.9+res->fp32 ; 3 bias->fp16
#define BM   128
#define BN   128
#define BKC  64
#define ROWB 144          /* 64 fp16 = 128B + 16B pad */
#define TILEB (128 * ROWB)     /* 18432 */
#define STAGEB (2 * TILEB)     /* 36864 */
#define GEMM_SMEM (2 * STAGEB) /* 73728 */

template <int EPI>
__global__ void __launch_bounds__(256, 2) gemm_mma(
    const __half* __restrict__ A_g, const __half* __restrict__ B_g,
    const float* __restrict__ bias, const float* __restrict__ res,
    float* __restrict__ Cf, __half* __restrict__ Ch,
    int M, int N, int K)
{
    extern __shared__ char dsm[];
    const uint32_t sbase = smem_u32(dsm);

    const int tid  = threadIdx.x;
    const int lane = tid & 31;
    const int wid  = tid >> 5;
    const int wm   = wid & 3;
    const int wn   = wid >> 2;
    const int m0   = blockIdx.y * BM;
    const int n0   = blockIdx.x * BN;

    const int a_row = lane & 15;
    const int a_col = (lane >> 4) << 3;
    const uint32_t offA = (uint32_t)((wm * 32 + a_row) * ROWB + a_col * 2);
    const int b_row = (lane & 7) | ((lane >> 4) << 3);
    const int b_col = ((lane >> 3) & 1) << 3;
    const uint32_t offB = (uint32_t)(TILEB + (wn * 64 + b_row) * ROWB + b_col * 2);

    float acc[2][8][4];
    #pragma unroll
    for (int i = 0; i < 2; i++)
        #pragma unroll
        for (int j = 0; j < 8; j++)
            #pragma unroll
            for (int k = 0; k < 4; k++) acc[i][j][k] = 0.f;

    const int ldu = K >> 3;
    const uint4* ga = (const uint4*)A_g;
    const uint4* gb = (const uint4*)B_g;

    const int nchunks = K / BKC;

    // per tile: 1024 uint4 -> 4 slots per thread (256 threads)
    auto issue = [&](int stage, int ch) {
        const int k0u = ch * (BKC / 8);
        const uint32_t so = sbase + (uint32_t)stage * STAGEB;
        #pragma unroll
        for (int i = 0; i < 4; i++) {
            const int idx = tid + i * 256;
            const int r = idx >> 3, q = idx & 7;
            const uint32_t d = so + (uint32_t)(r * ROWB + q * 16);
            cp_async16(d,         ga + (size_t)(m0 + r) * ldu + k0u + q);
            cp_async16(d + TILEB, gb + (size_t)(n0 + r) * ldu + k0u + q);
        }
    };

    issue(0, 0);
    CP_COMMIT();

    for (int ch = 0; ch < nchunks; ch++) {
        if (ch + 1 < nchunks) {
            issue((ch + 1) & 1, ch + 1);
            CP_COMMIT();
            CP_WAIT(1);
        } else {
            CP_WAIT(0);
        }
        __syncthreads();

        const uint32_t st = sbase + (uint32_t)(ch & 1) * STAGEB;
        const uint32_t aT = st + offA;
        const uint32_t bT = st + offB;

        #pragma unroll
        for (int ks = 0; ks < BKC; ks += 16) {
            uint32_t ah[2][4];
            #pragma unroll
            for (int mt = 0; mt < 2; mt++)
                ldsm_x4(ah[mt], aT + mt * (16 * ROWB) + ks * 2);
            #pragma unroll
            for (int np = 0; np < 4; np++) {
                uint32_t bh[4];
                ldsm_x4(bh, bT + np * (16 * ROWB) + ks * 2);
                #pragma unroll
                for (int mt = 0; mt < 2; mt++) {
                    mma16816(acc[mt][2 * np],     ah[mt], bh[0], bh[1]);
                    mma16816(acc[mt][2 * np + 1], ah[mt], bh[2], bh[3]);
                }
            }
        }
        __syncthreads();
    }

    // epilogue
    const int lr = lane >> 2;
    const int lc = (lane & 3) * 2;
    #pragma unroll
    for (int mt = 0; mt < 2; mt++) {
        #pragma unroll
        for (int nt = 0; nt < 8; nt++) {
            #pragma unroll
            for (int hh = 0; hh < 2; hh++) {
                const int gr = m0 + wm * 32 + mt * 16 + lr + hh * 8;
                const int gc = n0 + wn * 64 + nt * 8 + lc;
                float v0 = acc[mt][nt][hh * 2 + 0] + bias[gc];
                float v1 = acc[mt][nt][hh * 2 + 1] + bias[gc + 1];
                const size_t go = (size_t)gr * N + gc;
                if (EPI == 1) {
                    v0 = 0.5f * v0 * (1.0f + erff(v0 * 0.70710678118654752f));
                    v1 = 0.5f * v1 * (1.0f + erff(v1 * 0.70710678118654752f));
                    ((uint32_t*)Ch)[go >> 1] = pack_f16x2(v0, v1);
                } else if (EPI == 2) {
                    float2 rr = *(const float2*)&res[go];
                    float2 o2 = make_float2(v0 * SURV_ + rr.x, v1 * SURV_ + rr.y);
                    *(float2*)&Cf[go] = o2;
                } else {  // EPI == 3
                    ((uint32_t*)Ch)[go >> 1] = pack_f16x2(v0, v1);
                }
            }
        }
    }
}

// ---------------- Flash attention (fp16 MMA, q-tile 64, cp.async K/V) -------
// One CTA per (q_tile 64, head, batch); 128 threads (4 warps, 16 q-rows each).
#define FQT 64
#define KT  64
#define QB_  9216                  /* 64 rows * 144B */
#define KB_  9216
#define FLASH_SMEM (QB_ + 4 * KB_) /* Q + 2-stage K + 2-stage V = 46080 */

__global__ void __launch_bounds__(128) flash_mma(
    const __half* __restrict__ qkv, const float* __restrict__ x,
    float* __restrict__ x1)
{
    extern __shared__ char fsm[];
    const uint32_t sb = smem_u32(fsm);

    const int t = threadIdx.x;
    const int lane = t & 31, wid = t >> 5;
    const int qt = blockIdx.x, h = blockIdx.y, b = blockIdx.z;
    const size_t base = (size_t)b * P_ * D3_;
    const int q0 = qt * FQT, hc = h * 64;

    // load Q tile (64x64 fp16)
    #pragma unroll
    for (int i = 0; i < 4; i++) {
        int idx = t + i * 128;
        int r = idx >> 3, c8 = (idx & 7) << 3;
        *(uint4*)(fsm + r * 144 + c8 * 2) =
            *(const uint4*)(qkv + base + (size_t)(q0 + r) * D3_ + hc + c8);
    }

    auto issueKV = [&](int stage, int kt) {
        const int k0 = kt * KT;
        const uint32_t kb = sb + QB_ + (uint32_t)stage * KB_;
        const uint32_t vb = sb + QB_ + 2 * KB_ + (uint32_t)stage * KB_;
        #pragma unroll
        for (int i = 0; i < 4; i++) {
            int idx = t + i * 128;
            int r = idx >> 3, c8 = (idx & 7) << 3;
            cp_async16(kb + r * 144 + c8 * 2,
                       qkv + base + (size_t)(k0 + r) * D3_ + D_ + hc + c8);
            cp_async16(vb + r * 144 + c8 * 2,
                       qkv + base + (size_t)(k0 + r) * D3_ + 2 * D_ + hc + c8);
        }
    };

    issueKV(0, 0);
    CP_COMMIT();
    __syncthreads();

    // preload Q fragments (constant across kt)
    uint32_t qf[4][4];
    {
        const int qrow = wid * 16 + (lane & 15);
        const int qc = (lane >> 4) << 3;
        #pragma unroll
        for (int ks = 0; ks < 4; ks++)
            ldsm_x4(qf[ks], sb + qrow * 144 + (ks * 16 + qc) * 2);
    }

    float mrow[2] = {-1e30f, -1e30f};
    float lrow[2] = {0.f, 0.f};
    float o[8][4];
    #pragma unroll
    for (int i = 0; i < 8; i++)
        #pragma unroll
        for (int j = 0; j < 4; j++) o[i][j] = 0.f;

    const float SCL = 0.18033688011112042f;  // (1/8) * log2(e)

    const int krow = (lane & 7) + ((lane >> 4) << 3);
    const int kcol = ((lane >> 3) & 1) << 3;
    const int vrow = (lane & 7) + (((lane >> 3) & 1) << 3);
    const int vcol = (lane >> 4) << 3;

    const int niter = P_ / KT;
    for (int kt = 0; kt < niter; kt++) {
        if (kt + 1 < niter) {
            issueKV((kt + 1) & 1, kt + 1);
            CP_COMMIT();
            CP_WAIT(1);
        } else {
            CP_WAIT(0);
        }
        __syncthreads();

        const uint32_t kst = sb + QB_ + (uint32_t)(kt & 1) * KB_;
        const uint32_t vst = sb + QB_ + 2 * KB_ + (uint32_t)(kt & 1) * KB_;

        // S = Q @ K^T
        float s[8][4];
        #pragma unroll
        for (int i = 0; i < 8; i++)
            #pragma unroll
            for (int j = 0; j < 4; j++) s[i][j] = 0.f;
        #pragma unroll
        for (int ks = 0; ks < 4; ks++) {
            #pragma unroll
            for (int tp = 0; tp < 4; tp++) {
                uint32_t kf[4];
                ldsm_x4(kf, kst + (tp * 16 + krow) * 144 + (ks * 16 + kcol) * 2);
                mma16816(s[2 * tp],     qf[ks], kf[0], kf[1]);
                mma16816(s[2 * tp + 1], qf[ks], kf[2], kf[3]);
            }
        }

        // online softmax
        float pm[2] = {-1e30f, -1e30f};
        #pragma unroll
        for (int nt = 0; nt < 8; nt++) {
            pm[0] = fmaxf(pm[0], fmaxf(s[nt][0], s[nt][1]));
            pm[1] = fmaxf(pm[1], fmaxf(s[nt][2], s[nt][3]));
        }
        #pragma unroll
        for (int w = 0; w < 2; w++) {
            pm[w] = fmaxf(pm[w], __shfl_xor_sync(0xffffffffu, pm[w], 1));
            pm[w] = fmaxf(pm[w], __shfl_xor_sync(0xffffffffu, pm[w], 2));
        }
        float mn[2], f[2], sum[2];
        #pragma unroll
        for (int w = 0; w < 2; w++) {
            mn[w] = fmaxf(mrow[w], pm[w]);
            f[w]  = ex2f((mrow[w] - mn[w]) * SCL);
            sum[w] = 0.f;
        }
        #pragma unroll
        for (int nt = 0; nt < 8; nt++) {
            s[nt][0] = ex2f((s[nt][0] - mn[0]) * SCL);
            s[nt][1] = ex2f((s[nt][1] - mn[0]) * SCL);
            s[nt][2] = ex2f((s[nt][2] - mn[1]) * SCL);
            s[nt][3] = ex2f((s[nt][3] - mn[1]) * SCL);
            sum[0] += s[nt][0] + s[nt][1];
            sum[1] += s[nt][2] + s[nt][3];
        }
        #pragma unroll
        for (int w = 0; w < 2; w++) {
            sum[w] += __shfl_xor_sync(0xffffffffu, sum[w], 1);
            sum[w] += __shfl_xor_sync(0xffffffffu, sum[w], 2);
            lrow[w] = lrow[w] * f[w] + sum[w];
            mrow[w] = mn[w];
        }
        #pragma unroll
        for (int nt = 0; nt < 8; nt++) {
            o[nt][0] *= f[0]; o[nt][1] *= f[0];
            o[nt][2] *= f[1]; o[nt][3] *= f[1];
        }

        // P fragments (fp16) from S accumulators (layout identity)
        uint32_t pf[4][4];
        #pragma unroll
        for (int ks = 0; ks < 4; ks++) {
            pf[ks][0] = pack_f16x2(s[2 * ks][0],     s[2 * ks][1]);
            pf[ks][1] = pack_f16x2(s[2 * ks][2],     s[2 * ks][3]);
            pf[ks][2] = pack_f16x2(s[2 * ks + 1][0], s[2 * ks + 1][1]);
            pf[ks][3] = pack_f16x2(s[2 * ks + 1][2], s[2 * ks + 1][3]);
        }

        // O += P @ V
        #pragma unroll
        for (int ks = 0; ks < 4; ks++) {
            #pragma unroll
            for (int tp = 0; tp < 4; tp++) {
                uint32_t vf[4];
                ldsm_x4_t(vf, vst + (ks * 16 + vrow) * 144 + (tp * 16 + vcol) * 2);
                mma16816(o[2 * tp],     pf[ks], vf[0], vf[1]);
                mma16816(o[2 * tp + 1], pf[ks], vf[2], vf[3]);
            }
        }
        __syncthreads();
    }

    // finalize: /l, *0.9, + residual x
    const float inv0 = 1.0f / lrow[0];
    const float inv1 = 1.0f / lrow[1];
    const int r0 = q0 + wid * 16 + (lane >> 2);
    const size_t row0 = ((size_t)b * P_ + r0) * D_ + hc + (lane & 3) * 2;
    const size_t row1 = row0 + 8 * D_;
    #pragma unroll
    for (int nt = 0; nt < 8; nt++) {
        float2 xa = *(const float2*)&x[row0 + nt * 8];
        float2 ra;
        ra.x = o[nt][0] * inv0 * SURV_ + xa.x;
        ra.y = o[nt][1] * inv0 * SURV_ + xa.y;
        *(float2*)&x1[row0 + nt * 8] = ra;
        float2 xb = *(const float2*)&x[row1 + nt * 8];
        float2 rb;
        rb.x = o[nt][2] * inv1 * SURV_ + xb.x;
        rb.y = o[nt][3] * inv1 * SURV_ + xb.y;
        *(float2*)&x1[row1 + nt * 8] = rb;
    }
}

// ---------------- launch ----------------------------------------------------
extern "C" void kernel_launch(void* const* d_in, const int* in_sizes, int n_in,
                              void* d_out, int out_size)
{
    const float* x     = (const float*)d_in[0];
    const float* ln1_g = (const float*)d_in[1];
    const float* ln1_b = (const float*)d_in[2];
    const float* w_qkv = (const float*)d_in[3];
    const float* b_qkv = (const float*)d_in[4];
    const float* ln2_g = (const float*)d_in[5];
    const float* ln2_b = (const float*)d_in[6];
    const float* w1    = (const float*)d_in[7];
    const float* b1    = (const float*)d_in[8];
    const float* w2    = (const float*)d_in[9];
    const float* b2    = (const float*)d_in[10];
    float* out = (float*)d_out;

    __half *h, *qkvh, *ffn, *wq, *w1t, *w2t;
    float *x1;
    cudaGetSymbolAddress((void**)&h,    g_h);
    cudaGetSymbolAddress((void**)&qkvh, g_qkvh);
    cudaGetSymbolAddress((void**)&x1,   g_x1);
    cudaGetSymbolAddress((void**)&ffn,  g_ffn);
    cudaGetSymbolAddress((void**)&wq,   g_wq);
    cudaGetSymbolAddress((void**)&w1t,  g_w1);
    cudaGetSymbolAddress((void**)&w2t,  g_w2);

    cudaFuncSetAttribute(gemm_mma<1>,
                         cudaFuncAttributeMaxDynamicSharedMemorySize, GEMM_SMEM);
    cudaFuncSetAttribute(gemm_mma<2>,
                         cudaFuncAttributeMaxDynamicSharedMemorySize, GEMM_SMEM);
    cudaFuncSetAttribute(gemm_mma<3>,
                         cudaFuncAttributeMaxDynamicSharedMemorySize, GEMM_SMEM);
    cudaFuncSetAttribute(flash_mma,
                         cudaFuncAttributeMaxDynamicSharedMemorySize, FLASH_SMEM);

    // weight transpose + cast
    wcast_kernel<<<dim3(D3_ / 32, D_ / 32), 256>>>(w_qkv, wq, D_, D3_);
    wcast_kernel<<<dim3(DFF_ / 32, D_ / 32), 256>>>(w1, w1t, D_, DFF_);
    wcast_kernel<<<dim3(D_ / 32, DFF_ / 32), 256>>>(w2, w2t, DFF_, D_);

    // 1) LN1 -> fp16
    ln_f16_kernel<<<NTOK / 8, 256>>>(x, ln1_g, ln1_b, h);
    // 2) QKV projection -> fp16
    gemm_mma<3><<<dim3(D3_ / BN, NTOK / BM), 256, GEMM_SMEM>>>(
        h, wq, b_qkv, nullptr, nullptr, qkvh, NTOK, D3_, D_);
    // 3) attention + residual -> x1
    flash_mma<<<dim3(P_ / FQT, H_, B_), 128, FLASH_SMEM>>>(qkvh, x, x1);
    // 4) LN2 -> fp16
    ln_f16_kernel<<<NTOK / 8, 256>>>(x1, ln2_g, ln2_b, h);
    // 5) MLP up + GELU -> fp16
    gemm_mma<1><<<dim3(DFF_ / BN, NTOK / BM), 256, GEMM_SMEM>>>(
        h, w1t, b1, nullptr, nullptr, ffn, NTOK, DFF_, D_);
    // 6) MLP down + droppath + residual -> out
    gemm_mma<2><<<dim3(D_ / BN, NTOK / BM), 256, GEMM_SMEM>>>(
        ffn, w2t, b2, x1, out, nullptr, NTOK, D_, DFF_);
}

// round 9
// speedup vs baseline: 2.4181x; 1.0297x over previous
#include <cuda_runtime.h>
#include <cuda_fp16.h>
#include <math.h>
#include <stdint.h>

#define D_    768
#define P_    2048
#define B_    4
#define H_    12
#define DFF_  3072
#define NTOK  (B_ * P_)      /* 8192 */
#define D3_   (3 * D_)       /* 2304 */
#define EPS_  1e-3f
#define SURV_ 0.9f

// ---------------- scratch (static device globals) ---------------------------
__device__ __half g_h   [NTOK * D_];     // LN output, fp16
__device__ __half g_qkvh[NTOK * D3_];    // fp16 QKV
__device__ float  g_x1  [NTOK * D_];
__device__ __half g_ffn [NTOK * DFF_];   // MLP hidden, fp16
// transposed weights: [N, K] layout, fp16
__device__ __half g_wq[D3_ * D_];
__device__ __half g_w1[DFF_ * D_];
__device__ __half g_w2[D_ * DFF_];

// ---------------- helpers ----------------------------------------------------
__device__ __forceinline__ uint32_t smem_u32(const void* p) {
    uint32_t a;
    asm("{ .reg .u64 t; cvta.to.shared.u64 t, %1; cvt.u32.u64 %0, t; }"
        : "=r"(a) : "l"(p));
    return a;
}
__device__ __forceinline__ void ldsm_x4(uint32_t* r, uint32_t addr) {
    asm volatile("ldmatrix.sync.aligned.m8n8.x4.shared.b16 {%0,%1,%2,%3}, [%4];"
                 : "=r"(r[0]), "=r"(r[1]), "=r"(r[2]), "=r"(r[3]) : "r"(addr));
}
__device__ __forceinline__ void ldsm_x4_t(uint32_t* r, uint32_t addr) {
    asm volatile("ldmatrix.sync.aligned.m8n8.x4.trans.shared.b16 {%0,%1,%2,%3}, [%4];"
                 : "=r"(r[0]), "=r"(r[1]), "=r"(r[2]), "=r"(r[3]) : "r"(addr));
}
__device__ __forceinline__ void mma16816(float* c, const uint32_t* a,
                                         uint32_t b0, uint32_t b1) {
    asm volatile(
        "mma.sync.aligned.m16n8k16.row.col.f32.f16.f16.f32 "
        "{%0,%1,%2,%3}, {%4,%5,%6,%7}, {%8,%9}, {%0,%1,%2,%3};"
        : "+f"(c[0]), "+f"(c[1]), "+f"(c[2]), "+f"(c[3])
        : "r"(a[0]), "r"(a[1]), "r"(a[2]), "r"(a[3]), "r"(b0), "r"(b1));
}
__device__ __forceinline__ float ex2f(float x) {
    float y; asm("ex2.approx.f32 %0, %1;" : "=f"(y) : "f"(x)); return y;
}
__device__ __forceinline__ uint32_t h2ex2(uint32_t a) {
    uint32_t d; asm("ex2.approx.f16x2 %0, %1;" : "=r"(d) : "r"(a)); return d;
}
// packed fp16x2 = {lo half: first arg, hi half: second arg}
__device__ __forceinline__ uint32_t pack_f16x2(float lo, float hi) {
    uint32_t d;
    asm("cvt.rn.f16x2.f32 %0, %1, %2;" : "=r"(d) : "f"(hi), "f"(lo));
    return d;
}
__device__ __forceinline__ void cp_async16(uint32_t dst, const void* src) {
    asm volatile("cp.async.cg.shared.global [%0], [%1], 16;"
                 :: "r"(dst), "l"(src));
}
#define CP_COMMIT() asm volatile("cp.async.commit_group;" ::: "memory")
#define CP_WAIT(n)  asm volatile("cp.async.wait_group %0;" :: "n"(n) : "memory")
#define ONES2 0x3C003C00u   /* fp16x2 {1.0, 1.0} */

// ---------------- LayerNorm -> fp16 (warp-per-row) ---------------------------
__global__ void __launch_bounds__(256) ln_f16_kernel(
    const float* __restrict__ x, const float* __restrict__ g,
    const float* __restrict__ b, __half* __restrict__ out)
{
    const int row  = blockIdx.x * 8 + (threadIdx.x >> 5);
    const int lane = threadIdx.x & 31;
    const float4* xr = (const float4*)(x + (size_t)row * D_);
    const float4* gv = (const float4*)g;
    const float4* bv = (const float4*)b;

    float4 v[6];
    float s = 0.f;
    #pragma unroll
    for (int k = 0; k < 6; k++) {
        v[k] = xr[lane + 32 * k];
        s += v[k].x + v[k].y + v[k].z + v[k].w;
    }
    #pragma unroll
    for (int o = 16; o; o >>= 1) s += __shfl_xor_sync(0xffffffffu, s, o);
    const float mu = s * (1.0f / D_);

    float q = 0.f;
    #pragma unroll
    for (int k = 0; k < 6; k++) {
        v[k].x -= mu; v[k].y -= mu; v[k].z -= mu; v[k].w -= mu;
        q += v[k].x * v[k].x + v[k].y * v[k].y + v[k].z * v[k].z + v[k].w * v[k].w;
    }
    #pragma unroll
    for (int o = 16; o; o >>= 1) q += __shfl_xor_sync(0xffffffffu, q, o);
    const float rs = rsqrtf(q * (1.0f / D_) + EPS_);

    uint2* hp = (uint2*)(out + (size_t)row * D_);
    #pragma unroll
    for (int k = 0; k < 6; k++) {
        const int i4 = lane + 32 * k;
        float4 gg = gv[i4], bb = bv[i4];
        float o0 = v[k].x * rs * gg.x + bb.x;
        float o1 = v[k].y * rs * gg.y + bb.y;
        float o2 = v[k].z * rs * gg.z + bb.z;
        float o3 = v[k].w * rs * gg.w + bb.w;
        hp[i4] = make_uint2(pack_f16x2(o0, o1), pack_f16x2(o2, o3));
    }
}

// ---------------- weight transpose + cast: w[K,N] -> wt[N,K] fp16 -----------
__global__ void __launch_bounds__(256) wcast_kernel(
    const float* __restrict__ w, __half* __restrict__ wt, int K, int N)
{
    __shared__ float t[32][33];
    const int n0 = blockIdx.x * 32, k0 = blockIdx.y * 32;
    const int tx = threadIdx.x & 31, ty = threadIdx.x >> 5;
    #pragma unroll
    for (int j = 0; j < 4; j++) {
        int k = ty + j * 8;
        t[k][tx] = w[(size_t)(k0 + k) * N + n0 + tx];
    }
    __syncthreads();
    #pragma unroll
    for (int j = 0; j < 4; j++) {
        int n = ty + j * 8;
        wt[(size_t)(n0 + n) * K + k0 + tx] = __float2half(t[tx][n]);
    }
}

// ---------------- MMA GEMM: C[M,N] = A[M,K] @ B[N,K]^T, fp16 single-pass ----
// 128x128 tile, K chunk 64, 256 threads, 8 warps (4m x 2n), warp 32x64.
// cp.async 2-stage, 2 CTAs/SM.
// EPI: 1 bias+GELU->fp16 ; 2 bias,*0.9+res->fp32 ; 3 bias->fp16
#define BM   128
#define BN   128
#define BKC  64
#define ROWB 144          /* 64 fp16 = 128B + 16B pad */
#define TILEB (128 * ROWB)     /* 18432 */
#define STAGEB (2 * TILEB)     /* 36864 */
#define GEMM_SMEM (2 * STAGEB) /* 73728 */

template <int EPI>
__global__ void __launch_bounds__(256, 2) gemm_mma(
    const __half* __restrict__ A_g, const __half* __restrict__ B_g,
    const float* __restrict__ bias, const float* __restrict__ res,
    float* __restrict__ Cf, __half* __restrict__ Ch,
    int M, int N, int K)
{
    extern __shared__ char dsm[];
    const uint32_t sbase = smem_u32(dsm);

    const int tid  = threadIdx.x;
    const int lane = tid & 31;
    const int wid  = tid >> 5;
    const int wm   = wid & 3;
    const int wn   = wid >> 2;
    const int m0   = blockIdx.y * BM;
    const int n0   = blockIdx.x * BN;

    const int a_row = lane & 15;
    const int a_col = (lane >> 4) << 3;
    const uint32_t offA = (uint32_t)((wm * 32 + a_row) * ROWB + a_col * 2);
    const int b_row = (lane & 7) | ((lane >> 4) << 3);
    const int b_col = ((lane >> 3) & 1) << 3;
    const uint32_t offB = (uint32_t)(TILEB + (wn * 64 + b_row) * ROWB + b_col * 2);

    float acc[2][8][4];
    #pragma unroll
    for (int i = 0; i < 2; i++)
        #pragma unroll
        for (int j = 0; j < 8; j++)
            #pragma unroll
            for (int k = 0; k < 4; k++) acc[i][j][k] = 0.f;

    const int ldu = K >> 3;
    const uint4* ga = (const uint4*)A_g;
    const uint4* gb = (const uint4*)B_g;

    const int nchunks = K / BKC;

    auto issue = [&](int stage, int ch) {
        const int k0u = ch * (BKC / 8);
        const uint32_t so = sbase + (uint32_t)stage * STAGEB;
        #pragma unroll
        for (int i = 0; i < 4; i++) {
            const int idx = tid + i * 256;
            const int r = idx >> 3, q = idx & 7;
            const uint32_t d = so + (uint32_t)(r * ROWB + q * 16);
            cp_async16(d,         ga + (size_t)(m0 + r) * ldu + k0u + q);
            cp_async16(d + TILEB, gb + (size_t)(n0 + r) * ldu + k0u + q);
        }
    };

    issue(0, 0);
    CP_COMMIT();

    for (int ch = 0; ch < nchunks; ch++) {
        if (ch + 1 < nchunks) {
            issue((ch + 1) & 1, ch + 1);
            CP_COMMIT();
            CP_WAIT(1);
        } else {
            CP_WAIT(0);
        }
        __syncthreads();

        const uint32_t st = sbase + (uint32_t)(ch & 1) * STAGEB;
        const uint32_t aT = st + offA;
        const uint32_t bT = st + offB;

        #pragma unroll
        for (int ks = 0; ks < BKC; ks += 16) {
            uint32_t ah[2][4];
            #pragma unroll
            for (int mt = 0; mt < 2; mt++)
                ldsm_x4(ah[mt], aT + mt * (16 * ROWB) + ks * 2);
            #pragma unroll
            for (int np = 0; np < 4; np++) {
                uint32_t bh[4];
                ldsm_x4(bh, bT + np * (16 * ROWB) + ks * 2);
                #pragma unroll
                for (int mt = 0; mt < 2; mt++) {
                    mma16816(acc[mt][2 * np],     ah[mt], bh[0], bh[1]);
                    mma16816(acc[mt][2 * np + 1], ah[mt], bh[2], bh[3]);
                }
            }
        }
        __syncthreads();
    }

    // epilogue
    const int lr = lane >> 2;
    const int lc = (lane & 3) * 2;
    #pragma unroll
    for (int mt = 0; mt < 2; mt++) {
        #pragma unroll
        for (int nt = 0; nt < 8; nt++) {
            #pragma unroll
            for (int hh = 0; hh < 2; hh++) {
                const int gr = m0 + wm * 32 + mt * 16 + lr + hh * 8;
                const int gc = n0 + wn * 64 + nt * 8 + lc;
                float v0 = acc[mt][nt][hh * 2 + 0] + bias[gc];
                float v1 = acc[mt][nt][hh * 2 + 1] + bias[gc + 1];
                const size_t go = (size_t)gr * N + gc;
                if (EPI == 1) {
                    v0 = 0.5f * v0 * (1.0f + erff(v0 * 0.70710678118654752f));
                    v1 = 0.5f * v1 * (1.0f + erff(v1 * 0.70710678118654752f));
                    ((uint32_t*)Ch)[go >> 1] = pack_f16x2(v0, v1);
                } else if (EPI == 2) {
                    float2 rr = *(const float2*)&res[go];
                    float2 o2 = make_float2(v0 * SURV_ + rr.x, v1 * SURV_ + rr.y);
                    *(float2*)&Cf[go] = o2;
                } else {  // EPI == 3
                    ((uint32_t*)Ch)[go >> 1] = pack_f16x2(v0, v1);
                }
            }
        }
    }
}

// ---------------- Flash attention v2 ----------------------------------------
// q-tile 128, 4 warps x 32 q-rows (mt=2 strips): K/V fragment loads amortized
// over 4 MMAs each. fp16x2 ex2 softmax; row-sums via ones-MMA (exact fp32,
// consistent with fp16 P used in PV). cp.async 2-stage K/V.
#define FQT 128
#define KT  64
#define QB_  (128 * 144)           /* 18432 */
#define KB_  9216                  /* 64 rows * 144B */
#define FLASH_SMEM (QB_ + 4 * KB_) /* 55296 */

__global__ void __launch_bounds__(128) flash_mma(
    const __half* __restrict__ qkv, const float* __restrict__ x,
    float* __restrict__ x1)
{
    extern __shared__ char fsm[];
    const uint32_t sb = smem_u32(fsm);

    const int t = threadIdx.x;
    const int lane = t & 31, wid = t >> 5;
    const int qt = blockIdx.x, h = blockIdx.y, b = blockIdx.z;
    const size_t base = (size_t)b * P_ * D3_;
    const int q0 = qt * FQT, hc = h * 64;

    // load Q tile (128x64 fp16): 1024 uint4, 8 per thread
    #pragma unroll
    for (int i = 0; i < 8; i++) {
        int idx = t + i * 128;
        int r = idx >> 3, c8 = (idx & 7) << 3;
        *(uint4*)(fsm + r * 144 + c8 * 2) =
            *(const uint4*)(qkv + base + (size_t)(q0 + r) * D3_ + hc + c8);
    }

    auto issueKV = [&](int stage, int kt) {
        const int k0 = kt * KT;
        const uint32_t kb = sb + QB_ + (uint32_t)stage * KB_;
        const uint32_t vb = sb + QB_ + 2 * KB_ + (uint32_t)stage * KB_;
        #pragma unroll
        for (int i = 0; i < 4; i++) {
            int idx = t + i * 128;
            int r = idx >> 3, c8 = (idx & 7) << 3;
            cp_async16(kb + r * 144 + c8 * 2,
                       qkv + base + (size_t)(k0 + r) * D3_ + D_ + hc + c8);
            cp_async16(vb + r * 144 + c8 * 2,
                       qkv + base + (size_t)(k0 + r) * D3_ + 2 * D_ + hc + c8);
        }
    };

    issueKV(0, 0);
    CP_COMMIT();
    __syncthreads();

    // preload Q fragments: warp owns rows wid*32 + mt*16
    uint32_t qf[2][4][4];
    {
        const int qr = (lane & 15);
        const int qc = (lane >> 4) << 3;
        #pragma unroll
        for (int mt = 0; mt < 2; mt++)
            #pragma unroll
            for (int ks = 0; ks < 4; ks++)
                ldsm_x4(qf[mt][ks],
                        sb + (wid * 32 + mt * 16 + qr) * 144 + (ks * 16 + qc) * 2);
    }

    float mrow[2][2] = {{-1e30f, -1e30f}, {-1e30f, -1e30f}};
    float lrow[2][2] = {{0.f, 0.f}, {0.f, 0.f}};
    float o[2][8][4];
    #pragma unroll
    for (int m = 0; m < 2; m++)
        #pragma unroll
        for (int i = 0; i < 8; i++)
            #pragma unroll
            for (int j = 0; j < 4; j++) o[m][i][j] = 0.f;

    const float SCL = 0.18033688011112042f;  // (1/8) * log2(e)

    const int krow = (lane & 7) + ((lane >> 4) << 3);
    const int kcol = ((lane >> 3) & 1) << 3;
    const int vrow = (lane & 7) + (((lane >> 3) & 1) << 3);
    const int vcol = (lane >> 4) << 3;

    const int niter = P_ / KT;
    for (int kt = 0; kt < niter; kt++) {
        if (kt + 1 < niter) {
            issueKV((kt + 1) & 1, kt + 1);
            CP_COMMIT();
            CP_WAIT(1);
        } else {
            CP_WAIT(0);
        }
        __syncthreads();

        const uint32_t kst = sb + QB_ + (uint32_t)(kt & 1) * KB_;
        const uint32_t vst = sb + QB_ + 2 * KB_ + (uint32_t)(kt & 1) * KB_;

        // S = Q @ K^T (each kf feeds 4 MMAs across mt)
        float s[2][8][4];
        #pragma unroll
        for (int m = 0; m < 2; m++)
            #pragma unroll
            for (int i = 0; i < 8; i++)
                #pragma unroll
                for (int j = 0; j < 4; j++) s[m][i][j] = 0.f;
        #pragma unroll
        for (int ks = 0; ks < 4; ks++) {
            #pragma unroll
            for (int tp = 0; tp < 4; tp++) {
                uint32_t kf[4];
                ldsm_x4(kf, kst + (tp * 16 + krow) * 144 + (ks * 16 + kcol) * 2);
                #pragma unroll
                for (int mt = 0; mt < 2; mt++) {
                    mma16816(s[mt][2 * tp],     qf[mt][ks], kf[0], kf[1]);
                    mma16816(s[mt][2 * tp + 1], qf[mt][ks], kf[2], kf[3]);
                }
            }
        }

        // online softmax per mt strip; P fragments via f16x2 ex2
        uint32_t pf[2][4][4];
        #pragma unroll
        for (int mt = 0; mt < 2; mt++) {
            float pm0 = -1e30f, pm1 = -1e30f;
            #pragma unroll
            for (int nt = 0; nt < 8; nt++) {
                pm0 = fmaxf(pm0, fmaxf(s[mt][nt][0], s[mt][nt][1]));
                pm1 = fmaxf(pm1, fmaxf(s[mt][nt][2], s[mt][nt][3]));
            }
            pm0 = fmaxf(pm0, __shfl_xor_sync(0xffffffffu, pm0, 1));
            pm0 = fmaxf(pm0, __shfl_xor_sync(0xffffffffu, pm0, 2));
            pm1 = fmaxf(pm1, __shfl_xor_sync(0xffffffffu, pm1, 1));
            pm1 = fmaxf(pm1, __shfl_xor_sync(0xffffffffu, pm1, 2));
            const float mn0 = fmaxf(mrow[mt][0], pm0);
            const float mn1 = fmaxf(mrow[mt][1], pm1);
            const float f0 = ex2f((mrow[mt][0] - mn0) * SCL);
            const float f1 = ex2f((mrow[mt][1] - mn1) * SCL);

            #pragma unroll
            for (int ks = 0; ks < 4; ks++) {
                pf[mt][ks][0] = h2ex2(pack_f16x2((s[mt][2 * ks][0] - mn0) * SCL,
                                                 (s[mt][2 * ks][1] - mn0) * SCL));
                pf[mt][ks][1] = h2ex2(pack_f16x2((s[mt][2 * ks][2] - mn1) * SCL,
                                                 (s[mt][2 * ks][3] - mn1) * SCL));
                pf[mt][ks][2] = h2ex2(pack_f16x2((s[mt][2 * ks + 1][0] - mn0) * SCL,
                                                 (s[mt][2 * ks + 1][1] - mn0) * SCL));
                pf[mt][ks][3] = h2ex2(pack_f16x2((s[mt][2 * ks + 1][2] - mn1) * SCL,
                                                 (s[mt][2 * ks + 1][3] - mn1) * SCL));
            }

            // row sums via ones-MMA (la[0]=row lr, la[2]=row lr+8)
            float la[4] = {0.f, 0.f, 0.f, 0.f};
            #pragma unroll
            for (int ks = 0; ks < 4; ks++)
                mma16816(la, pf[mt][ks], ONES2, ONES2);

            lrow[mt][0] = lrow[mt][0] * f0 + la[0];
            lrow[mt][1] = lrow[mt][1] * f1 + la[2];
            mrow[mt][0] = mn0;
            mrow[mt][1] = mn1;

            #pragma unroll
            for (int nt = 0; nt < 8; nt++) {
                o[mt][nt][0] *= f0; o[mt][nt][1] *= f0;
                o[mt][nt][2] *= f1; o[mt][nt][3] *= f1;
            }
        }

        // O += P @ V (each vf feeds 4 MMAs across mt)
        #pragma unroll
        for (int ks = 0; ks < 4; ks++) {
            #pragma unroll
            for (int tp = 0; tp < 4; tp++) {
                uint32_t vf[4];
                ldsm_x4_t(vf, vst + (ks * 16 + vrow) * 144 + (tp * 16 + vcol) * 2);
                #pragma unroll
                for (int mt = 0; mt < 2; mt++) {
                    mma16816(o[mt][2 * tp],     pf[mt][ks], vf[0], vf[1]);
                    mma16816(o[mt][2 * tp + 1], pf[mt][ks], vf[2], vf[3]);
                }
            }
        }
        __syncthreads();
    }

    // finalize: /l, *0.9, + residual x
    #pragma unroll
    for (int mt = 0; mt < 2; mt++) {
        const float inv0 = 1.0f / lrow[mt][0];
        const float inv1 = 1.0f / lrow[mt][1];
        const int r0 = q0 + wid * 32 + mt * 16 + (lane >> 2);
        const size_t row0 = ((size_t)b * P_ + r0) * D_ + hc + (lane & 3) * 2;
        const size_t row1 = row0 + 8 * D_;
        #pragma unroll
        for (int nt = 0; nt < 8; nt++) {
            float2 xa = *(const float2*)&x[row0 + nt * 8];
            float2 ra;
            ra.x = o[mt][nt][0] * inv0 * SURV_ + xa.x;
            ra.y = o[mt][nt][1] * inv0 * SURV_ + xa.y;
            *(float2*)&x1[row0 + nt * 8] = ra;
            float2 xb = *(const float2*)&x[row1 + nt * 8];
            float2 rb;
            rb.x = o[mt][nt][2] * inv1 * SURV_ + xb.x;
            rb.y = o[mt][nt][3] * inv1 * SURV_ + xb.y;
            *(float2*)&x1[row1 + nt * 8] = rb;
        }
    }
}

// ---------------- launch ----------------------------------------------------
extern "C" void kernel_launch(void* const* d_in, const int* in_sizes, int n_in,
                              void* d_out, int out_size)
{
    const float* x     = (const float*)d_in[0];
    const float* ln1_g = (const float*)d_in[1];
    const float* ln1_b = (const float*)d_in[2];
    const float* w_qkv = (const float*)d_in[3];
    const float* b_qkv = (const float*)d_in[4];
    const float* ln2_g = (const float*)d_in[5];
    const float* ln2_b = (const float*)d_in[6];
    const float* w1    = (const float*)d_in[7];
    const float* b1    = (const float*)d_in[8];
    const float* w2    = (const float*)d_in[9];
    const float* b2    = (const float*)d_in[10];
    float* out = (float*)d_out;

    __half *h, *qkvh, *ffn, *wq, *w1t, *w2t;
    float *x1;
    cudaGetSymbolAddress((void**)&h,    g_h);
    cudaGetSymbolAddress((void**)&qkvh, g_qkvh);
    cudaGetSymbolAddress((void**)&x1,   g_x1);
    cudaGetSymbolAddress((void**)&ffn,  g_ffn);
    cudaGetSymbolAddress((void**)&wq,   g_wq);
    cudaGetSymbolAddress((void**)&w1t,  g_w1);
    cudaGetSymbolAddress((void**)&w2t,  g_w2);

    cudaFuncSetAttribute(gemm_mma<1>,
                         cudaFuncAttributeMaxDynamicSharedMemorySize, GEMM_SMEM);
    cudaFuncSetAttribute(gemm_mma<2>,
                         cudaFuncAttributeMaxDynamicSharedMemorySize, GEMM_SMEM);
    cudaFuncSetAttribute(gemm_mma<3>,
                         cudaFuncAttributeMaxDynamicSharedMemorySize, GEMM_SMEM);
    cudaFuncSetAttribute(flash_mma,
                         cudaFuncAttributeMaxDynamicSharedMemorySize, FLASH_SMEM);

    // weight transpose + cast
    wcast_kernel<<<dim3(D3_ / 32, D_ / 32), 256>>>(w_qkv, wq, D_, D3_);
    wcast_kernel<<<dim3(DFF_ / 32, D_ / 32), 256>>>(w1, w1t, D_, DFF_);
    wcast_kernel<<<dim3(D_ / 32, DFF_ / 32), 256>>>(w2, w2t, DFF_, D_);

    // 1) LN1 -> fp16
    ln_f16_kernel<<<NTOK / 8, 256>>>(x, ln1_g, ln1_b, h);
    // 2) QKV projection -> fp16
    gemm_mma<3><<<dim3(D3_ / BN, NTOK / BM), 256, GEMM_SMEM>>>(
        h, wq, b_qkv, nullptr, nullptr, qkvh, NTOK, D3_, D_);
    // 3) attention + residual -> x1
    flash_mma<<<dim3(P_ / FQT, H_, B_), 128, FLASH_SMEM>>>(qkvh, x, x1);
    // 4) LN2 -> fp16
    ln_f16_kernel<<<NTOK / 8, 256>>>(x1, ln2_g, ln2_b, h);
    // 5) MLP up + GELU -> fp16
    gemm_mma<1><<<dim3(DFF_ / BN, NTOK / BM), 256, GEMM_SMEM>>>(
        h, w1t, b1, nullptr, nullptr, ffn, NTOK, DFF_, D_);
    // 6) MLP down + droppath + residual -> out
    gemm_mma<2><<<dim3(D_ / BN, NTOK / BM), 256, GEMM_SMEM>>>(
        ffn, w2t, b2, x1, out, nullptr, NTOK, D_, DFF_);
}

// round 10
// speedup vs baseline: 2.4233x; 1.0022x over previous
#include <cuda_runtime.h>
#include <cuda_fp16.h>
#include <math.h>
#include <stdint.h>

#define D_    768
#define P_    2048
#define B_    4
#define H_    12
#define DFF_  3072
#define NTOK  (B_ * P_)      /* 8192 */
#define D3_   (3 * D_)       /* 2304 */
#define EPS_  1e-3f
#define SURV_ 0.9f

// ---------------- scratch (static device globals) ---------------------------
__device__ __half g_h   [NTOK * D_];     // LN output, fp16
__device__ __half g_qkvh[NTOK * D3_];    // fp16 QKV
__device__ float  g_x1  [NTOK * D_];
__device__ __half g_ffn [NTOK * DFF_];   // MLP hidden, fp16
// transposed weights: [N, K] layout, fp16
__device__ __half g_wq[D3_ * D_];
__device__ __half g_w1[DFF_ * D_];
__device__ __half g_w2[D_ * DFF_];

// ---------------- helpers ----------------------------------------------------
__device__ __forceinline__ uint32_t smem_u32(const void* p) {
    uint32_t a;
    asm("{ .reg .u64 t; cvta.to.shared.u64 t, %1; cvt.u32.u64 %0, t; }"
        : "=r"(a) : "l"(p));
    return a;
}
__device__ __forceinline__ void ldsm_x4(uint32_t* r, uint32_t addr) {
    asm volatile("ldmatrix.sync.aligned.m8n8.x4.shared.b16 {%0,%1,%2,%3}, [%4];"
                 : "=r"(r[0]), "=r"(r[1]), "=r"(r[2]), "=r"(r[3]) : "r"(addr));
}
__device__ __forceinline__ void ldsm_x4_t(uint32_t* r, uint32_t addr) {
    asm volatile("ldmatrix.sync.aligned.m8n8.x4.trans.shared.b16 {%0,%1,%2,%3}, [%4];"
                 : "=r"(r[0]), "=r"(r[1]), "=r"(r[2]), "=r"(r[3]) : "r"(addr));
}
__device__ __forceinline__ void mma16816(float* c, const uint32_t* a,
                                         uint32_t b0, uint32_t b1) {
    asm volatile(
        "mma.sync.aligned.m16n8k16.row.col.f32.f16.f16.f32 "
        "{%0,%1,%2,%3}, {%4,%5,%6,%7}, {%8,%9}, {%0,%1,%2,%3};"
        : "+f"(c[0]), "+f"(c[1]), "+f"(c[2]), "+f"(c[3])
        : "r"(a[0]), "r"(a[1]), "r"(a[2]), "r"(a[3]), "r"(b0), "r"(b1));
}
__device__ __forceinline__ float ex2f(float x) {
    float y; asm("ex2.approx.f32 %0, %1;" : "=f"(y) : "f"(x)); return y;
}
__device__ __forceinline__ uint32_t h2ex2(uint32_t a) {
    uint32_t d; asm("ex2.approx.f16x2 %0, %1;" : "=r"(d) : "r"(a)); return d;
}
// packed fp16x2 = {lo half: first arg, hi half: second arg}
__device__ __forceinline__ uint32_t pack_f16x2(float lo, float hi) {
    uint32_t d;
    asm("cvt.rn.f16x2.f32 %0, %1, %2;" : "=r"(d) : "f"(hi), "f"(lo));
    return d;
}
__device__ __forceinline__ void cp_async16(uint32_t dst, const void* src) {
    asm volatile("cp.async.cg.shared.global [%0], [%1], 16;"
                 :: "r"(dst), "l"(src));
}
#define CP_COMMIT() asm volatile("cp.async.commit_group;" ::: "memory")
#define CP_WAIT(n)  asm volatile("cp.async.wait_group %0;" :: "n"(n) : "memory")
#define ONES2 0x3C003C00u   /* fp16x2 {1.0, 1.0} */

// ---------------- LayerNorm -> fp16 (warp-per-row) ---------------------------
__global__ void __launch_bounds__(256) ln_f16_kernel(
    const float* __restrict__ x, const float* __restrict__ g,
    const float* __restrict__ b, __half* __restrict__ out)
{
    const int row  = blockIdx.x * 8 + (threadIdx.x >> 5);
    const int lane = threadIdx.x & 31;
    const float4* xr = (const float4*)(x + (size_t)row * D_);
    const float4* gv = (const float4*)g;
    const float4* bv = (const float4*)b;

    float4 v[6];
    float s = 0.f;
    #pragma unroll
    for (int k = 0; k < 6; k++) {
        v[k] = xr[lane + 32 * k];
        s += v[k].x + v[k].y + v[k].z + v[k].w;
    }
    #pragma unroll
    for (int o = 16; o; o >>= 1) s += __shfl_xor_sync(0xffffffffu, s, o);
    const float mu = s * (1.0f / D_);

    float q = 0.f;
    #pragma unroll
    for (int k = 0; k < 6; k++) {
        v[k].x -= mu; v[k].y -= mu; v[k].z -= mu; v[k].w -= mu;
        q += v[k].x * v[k].x + v[k].y * v[k].y + v[k].z * v[k].z + v[k].w * v[k].w;
    }
    #pragma unroll
    for (int o = 16; o; o >>= 1) q += __shfl_xor_sync(0xffffffffu, q, o);
    const float rs = rsqrtf(q * (1.0f / D_) + EPS_);

    uint2* hp = (uint2*)(out + (size_t)row * D_);
    #pragma unroll
    for (int k = 0; k < 6; k++) {
        const int i4 = lane + 32 * k;
        float4 gg = gv[i4], bb = bv[i4];
        float o0 = v[k].x * rs * gg.x + bb.x;
        float o1 = v[k].y * rs * gg.y + bb.y;
        float o2 = v[k].z * rs * gg.z + bb.z;
        float o3 = v[k].w * rs * gg.w + bb.w;
        hp[i4] = make_uint2(pack_f16x2(o0, o1), pack_f16x2(o2, o3));
    }
}

// ---------------- weight transpose + cast: w[K,N] -> wt[N,K] fp16 -----------
__global__ void __launch_bounds__(256) wcast_kernel(
    const float* __restrict__ w, __half* __restrict__ wt, int K, int N)
{
    __shared__ float t[32][33];
    const int n0 = blockIdx.x * 32, k0 = blockIdx.y * 32;
    const int tx = threadIdx.x & 31, ty = threadIdx.x >> 5;
    #pragma unroll
    for (int j = 0; j < 4; j++) {
        int k = ty + j * 8;
        t[k][tx] = w[(size_t)(k0 + k) * N + n0 + tx];
    }
    __syncthreads();
    #pragma unroll
    for (int j = 0; j < 4; j++) {
        int n = ty + j * 8;
        wt[(size_t)(n0 + n) * K + k0 + tx] = __float2half(t[tx][n]);
    }
}

// ---------------- MMA GEMM: C[M,N] = A[M,K] @ B[N,K]^T, fp16 single-pass ----
// 128x128 tile, K chunk 64, 256 threads, 8 warps (4m x 2n), warp 32x64.
// cp.async 2-stage, 2 CTAs/SM.
// EPI: 1 bias+GELU->fp16 ; 2 bias,*0.9+res->fp32 ; 3 bias->fp16
#define BM   128
#define BN   128
#define BKC  64
#define ROWB 144          /* 64 fp16 = 128B + 16B pad */
#define TILEB (128 * ROWB)     /* 18432 */
#define STAGEB (2 * TILEB)     /* 36864 */
#define GEMM_SMEM (2 * STAGEB) /* 73728 */

template <int EPI>
__global__ void __launch_bounds__(256, 2) gemm_mma(
    const __half* __restrict__ A_g, const __half* __restrict__ B_g,
    const float* __restrict__ bias, const float* __restrict__ res,
    float* __restrict__ Cf, __half* __restrict__ Ch,
    int M, int N, int K)
{
    extern __shared__ char dsm[];
    const uint32_t sbase = smem_u32(dsm);

    const int tid  = threadIdx.x;
    const int lane = tid & 31;
    const int wid  = tid >> 5;
    const int wm   = wid & 3;
    const int wn   = wid >> 2;
    const int m0   = blockIdx.y * BM;
    const int n0   = blockIdx.x * BN;

    const int a_row = lane & 15;
    const int a_col = (lane >> 4) << 3;
    const uint32_t offA = (uint32_t)((wm * 32 + a_row) * ROWB + a_col * 2);
    const int b_row = (lane & 7) | ((lane >> 4) << 3);
    const int b_col = ((lane >> 3) & 1) << 3;
    const uint32_t offB = (uint32_t)(TILEB + (wn * 64 + b_row) * ROWB + b_col * 2);

    float acc[2][8][4];
    #pragma unroll
    for (int i = 0; i < 2; i++)
        #pragma unroll
        for (int j = 0; j < 8; j++)
            #pragma unroll
            for (int k = 0; k < 4; k++) acc[i][j][k] = 0.f;

    const int ldu = K >> 3;
    const uint4* ga = (const uint4*)A_g;
    const uint4* gb = (const uint4*)B_g;

    const int nchunks = K / BKC;

    auto issue = [&](int stage, int ch) {
        const int k0u = ch * (BKC / 8);
        const uint32_t so = sbase + (uint32_t)stage * STAGEB;
        #pragma unroll
        for (int i = 0; i < 4; i++) {
            const int idx = tid + i * 256;
            const int r = idx >> 3, q = idx & 7;
            const uint32_t d = so + (uint32_t)(r * ROWB + q * 16);
            cp_async16(d,         ga + (size_t)(m0 + r) * ldu + k0u + q);
            cp_async16(d + TILEB, gb + (size_t)(n0 + r) * ldu + k0u + q);
        }
    };

    issue(0, 0);
    CP_COMMIT();

    for (int ch = 0; ch < nchunks; ch++) {
        if (ch + 1 < nchunks) {
            issue((ch + 1) & 1, ch + 1);
            CP_COMMIT();
            CP_WAIT(1);
        } else {
            CP_WAIT(0);
        }
        __syncthreads();

        const uint32_t st = sbase + (uint32_t)(ch & 1) * STAGEB;
        const uint32_t aT = st + offA;
        const uint32_t bT = st + offB;

        #pragma unroll
        for (int ks = 0; ks < BKC; ks += 16) {
            uint32_t ah[2][4];
            #pragma unroll
            for (int mt = 0; mt < 2; mt++)
                ldsm_x4(ah[mt], aT + mt * (16 * ROWB) + ks * 2);
            #pragma unroll
            for (int np = 0; np < 4; np++) {
                uint32_t bh[4];
                ldsm_x4(bh, bT + np * (16 * ROWB) + ks * 2);
                #pragma unroll
                for (int mt = 0; mt < 2; mt++) {
                    mma16816(acc[mt][2 * np],     ah[mt], bh[0], bh[1]);
                    mma16816(acc[mt][2 * np + 1], ah[mt], bh[2], bh[3]);
                }
            }
        }
        __syncthreads();
    }

    // epilogue
    const int lr = lane >> 2;
    const int lc = (lane & 3) * 2;
    #pragma unroll
    for (int mt = 0; mt < 2; mt++) {
        #pragma unroll
        for (int nt = 0; nt < 8; nt++) {
            #pragma unroll
            for (int hh = 0; hh < 2; hh++) {
                const int gr = m0 + wm * 32 + mt * 16 + lr + hh * 8;
                const int gc = n0 + wn * 64 + nt * 8 + lc;
                float v0 = acc[mt][nt][hh * 2 + 0] + bias[gc];
                float v1 = acc[mt][nt][hh * 2 + 1] + bias[gc + 1];
                const size_t go = (size_t)gr * N + gc;
                if (EPI == 1) {
                    v0 = 0.5f * v0 * (1.0f + erff(v0 * 0.70710678118654752f));
                    v1 = 0.5f * v1 * (1.0f + erff(v1 * 0.70710678118654752f));
                    ((uint32_t*)Ch)[go >> 1] = pack_f16x2(v0, v1);
                } else if (EPI == 2) {
                    float2 rr = *(const float2*)&res[go];
                    float2 o2 = make_float2(v0 * SURV_ + rr.x, v1 * SURV_ + rr.y);
                    *(float2*)&Cf[go] = o2;
                } else {  // EPI == 3
                    ((uint32_t*)Ch)[go >> 1] = pack_f16x2(v0, v1);
                }
            }
        }
    }
}

// ---------------- Flash attention v3 ----------------------------------------
// q-tile 64, 4 warps x 16 q-rows, 128 threads: ~130 regs -> 3 CTAs/SM
// (12 warps/SM). f16x2 ex2 softmax; row-sums via ones-MMA. cp.async K/V.
#define FQT 64
#define KT  64
#define QB_  9216                  /* 64 rows * 144B */
#define KB_  9216
#define FLASH_SMEM (QB_ + 4 * KB_) /* 46080 */

__global__ void __launch_bounds__(128) flash_mma(
    const __half* __restrict__ qkv, const float* __restrict__ x,
    float* __restrict__ x1)
{
    extern __shared__ char fsm[];
    const uint32_t sb = smem_u32(fsm);

    const int t = threadIdx.x;
    const int lane = t & 31, wid = t >> 5;
    const int qt = blockIdx.x, h = blockIdx.y, b = blockIdx.z;
    const size_t base = (size_t)b * P_ * D3_;
    const int q0 = qt * FQT, hc = h * 64;

    // load Q tile (64x64 fp16): 512 uint4, 4 per thread
    #pragma unroll
    for (int i = 0; i < 4; i++) {
        int idx = t + i * 128;
        int r = idx >> 3, c8 = (idx & 7) << 3;
        *(uint4*)(fsm + r * 144 + c8 * 2) =
            *(const uint4*)(qkv + base + (size_t)(q0 + r) * D3_ + hc + c8);
    }

    auto issueKV = [&](int stage, int kt) {
        const int k0 = kt * KT;
        const uint32_t kb = sb + QB_ + (uint32_t)stage * KB_;
        const uint32_t vb = sb + QB_ + 2 * KB_ + (uint32_t)stage * KB_;
        #pragma unroll
        for (int i = 0; i < 4; i++) {
            int idx = t + i * 128;
            int r = idx >> 3, c8 = (idx & 7) << 3;
            cp_async16(kb + r * 144 + c8 * 2,
                       qkv + base + (size_t)(k0 + r) * D3_ + D_ + hc + c8);
            cp_async16(vb + r * 144 + c8 * 2,
                       qkv + base + (size_t)(k0 + r) * D3_ + 2 * D_ + hc + c8);
        }
    };

    issueKV(0, 0);
    CP_COMMIT();
    __syncthreads();

    // preload Q fragments (constant across kt); warp owns rows wid*16..+15
    uint32_t qf[4][4];
    {
        const int qr = lane & 15;
        const int qc = (lane >> 4) << 3;
        #pragma unroll
        for (int ks = 0; ks < 4; ks++)
            ldsm_x4(qf[ks], sb + (wid * 16 + qr) * 144 + (ks * 16 + qc) * 2);
    }

    float mrow[2] = {-1e30f, -1e30f};
    float lrow[2] = {0.f, 0.f};
    float o[8][4];
    #pragma unroll
    for (int i = 0; i < 8; i++)
        #pragma unroll
        for (int j = 0; j < 4; j++) o[i][j] = 0.f;

    const float SCL = 0.18033688011112042f;  // (1/8) * log2(e)

    const int krow = (lane & 7) + ((lane >> 4) << 3);
    const int kcol = ((lane >> 3) & 1) << 3;
    const int vrow = (lane & 7) + (((lane >> 3) & 1) << 3);
    const int vcol = (lane >> 4) << 3;

    const int niter = P_ / KT;
    for (int kt = 0; kt < niter; kt++) {
        if (kt + 1 < niter) {
            issueKV((kt + 1) & 1, kt + 1);
            CP_COMMIT();
            CP_WAIT(1);
        } else {
            CP_WAIT(0);
        }
        __syncthreads();

        const uint32_t kst = sb + QB_ + (uint32_t)(kt & 1) * KB_;
        const uint32_t vst = sb + QB_ + 2 * KB_ + (uint32_t)(kt & 1) * KB_;

        // S = Q @ K^T
        float s[8][4];
        #pragma unroll
        for (int i = 0; i < 8; i++)
            #pragma unroll
            for (int j = 0; j < 4; j++) s[i][j] = 0.f;
        #pragma unroll
        for (int ks = 0; ks < 4; ks++) {
            #pragma unroll
            for (int tp = 0; tp < 4; tp++) {
                uint32_t kf[4];
                ldsm_x4(kf, kst + (tp * 16 + krow) * 144 + (ks * 16 + kcol) * 2);
                mma16816(s[2 * tp],     qf[ks], kf[0], kf[1]);
                mma16816(s[2 * tp + 1], qf[ks], kf[2], kf[3]);
            }
        }

        // online softmax: rows lr and lr+8; P via f16x2 ex2
        float pm0 = -1e30f, pm1 = -1e30f;
        #pragma unroll
        for (int nt = 0; nt < 8; nt++) {
            pm0 = fmaxf(pm0, fmaxf(s[nt][0], s[nt][1]));
            pm1 = fmaxf(pm1, fmaxf(s[nt][2], s[nt][3]));
        }
        pm0 = fmaxf(pm0, __shfl_xor_sync(0xffffffffu, pm0, 1));
        pm0 = fmaxf(pm0, __shfl_xor_sync(0xffffffffu, pm0, 2));
        pm1 = fmaxf(pm1, __shfl_xor_sync(0xffffffffu, pm1, 1));
        pm1 = fmaxf(pm1, __shfl_xor_sync(0xffffffffu, pm1, 2));
        const float mn0 = fmaxf(mrow[0], pm0);
        const float mn1 = fmaxf(mrow[1], pm1);
        const float f0 = ex2f((mrow[0] - mn0) * SCL);
        const float f1 = ex2f((mrow[1] - mn1) * SCL);

        uint32_t pf[4][4];
        #pragma unroll
        for (int ks = 0; ks < 4; ks++) {
            pf[ks][0] = h2ex2(pack_f16x2((s[2 * ks][0] - mn0) * SCL,
                                         (s[2 * ks][1] - mn0) * SCL));
            pf[ks][1] = h2ex2(pack_f16x2((s[2 * ks][2] - mn1) * SCL,
                                         (s[2 * ks][3] - mn1) * SCL));
            pf[ks][2] = h2ex2(pack_f16x2((s[2 * ks + 1][0] - mn0) * SCL,
                                         (s[2 * ks + 1][1] - mn0) * SCL));
            pf[ks][3] = h2ex2(pack_f16x2((s[2 * ks + 1][2] - mn1) * SCL,
                                         (s[2 * ks + 1][3] - mn1) * SCL));
        }

        // row sums via ones-MMA (la[0]=row lr, la[2]=row lr+8)
        float la[4] = {0.f, 0.f, 0.f, 0.f};
        #pragma unroll
        for (int ks = 0; ks < 4; ks++)
            mma16816(la, pf[ks], ONES2, ONES2);

        lrow[0] = lrow[0] * f0 + la[0];
        lrow[1] = lrow[1] * f1 + la[2];
        mrow[0] = mn0;
        mrow[1] = mn1;

        #pragma unroll
        for (int nt = 0; nt < 8; nt++) {
            o[nt][0] *= f0; o[nt][1] *= f0;
            o[nt][2] *= f1; o[nt][3] *= f1;
        }

        // O += P @ V
        #pragma unroll
        for (int ks = 0; ks < 4; ks++) {
            #pragma unroll
            for (int tp = 0; tp < 4; tp++) {
                uint32_t vf[4];
                ldsm_x4_t(vf, vst + (ks * 16 + vrow) * 144 + (tp * 16 + vcol) * 2);
                mma16816(o[2 * tp],     pf[ks], vf[0], vf[1]);
                mma16816(o[2 * tp + 1], pf[ks], vf[2], vf[3]);
            }
        }
        __syncthreads();
    }

    // finalize: /l, *0.9, + residual x
    const float inv0 = 1.0f / lrow[0];
    const float inv1 = 1.0f / lrow[1];
    const int r0 = q0 + wid * 16 + (lane >> 2);
    const size_t row0 = ((size_t)b * P_ + r0) * D_ + hc + (lane & 3) * 2;
    const size_t row1 = row0 + 8 * D_;
    #pragma unroll
    for (int nt = 0; nt < 8; nt++) {
        float2 xa = *(const float2*)&x[row0 + nt * 8];
        float2 ra;
        ra.x = o[nt][0] * inv0 * SURV_ + xa.x;
        ra.y = o[nt][1] * inv0 * SURV_ + xa.y;
        *(float2*)&x1[row0 + nt * 8] = ra;
        float2 xb = *(const float2*)&x[row1 + nt * 8];
        float2 rb;
        rb.x = o[nt][2] * inv1 * SURV_ + xb.x;
        rb.y = o[nt][3] * inv1 * SURV_ + xb.y;
        *(float2*)&x1[row1 + nt * 8] = rb;
    }
}

// ---------------- launch ----------------------------------------------------
extern "C" void kernel_launch(void* const* d_in, const int* in_sizes, int n_in,
                              void* d_out, int out_size)
{
    const float* x     = (const float*)d_in[0];
    const float* ln1_g = (const float*)d_in[1];
    const float* ln1_b = (const float*)d_in[2];
    const float* w_qkv = (const float*)d_in[3];
    const float* b_qkv = (const float*)d_in[4];
    const float* ln2_g = (const float*)d_in[5];
    const float* ln2_b = (const float*)d_in[6];
    const float* w1    = (const float*)d_in[7];
    const float* b1    = (const float*)d_in[8];
    const float* w2    = (const float*)d_in[9];
    const float* b2    = (const float*)d_in[10];
    float* out = (float*)d_out;

    __half *h, *qkvh, *ffn, *wq, *w1t, *w2t;
    float *x1;
    cudaGetSymbolAddress((void**)&h,    g_h);
    cudaGetSymbolAddress((void**)&qkvh, g_qkvh);
    cudaGetSymbolAddress((void**)&x1,   g_x1);
    cudaGetSymbolAddress((void**)&ffn,  g_ffn);
    cudaGetSymbolAddress((void**)&wq,   g_wq);
    cudaGetSymbolAddress((void**)&w1t,  g_w1);
    cudaGetSymbolAddress((void**)&w2t,  g_w2);

    cudaFuncSetAttribute(gemm_mma<1>,
                         cudaFuncAttributeMaxDynamicSharedMemorySize, GEMM_SMEM);
    cudaFuncSetAttribute(gemm_mma<2>,
                         cudaFuncAttributeMaxDynamicSharedMemorySize, GEMM_SMEM);
    cudaFuncSetAttribute(gemm_mma<3>,
                         cudaFuncAttributeMaxDynamicSharedMemorySize, GEMM_SMEM);
    cudaFuncSetAttribute(flash_mma,
                         cudaFuncAttributeMaxDynamicSharedMemorySize, FLASH_SMEM);

    // weight transpose + cast
    wcast_kernel<<<dim3(D3_ / 32, D_ / 32), 256>>>(w_qkv, wq, D_, D3_);
    wcast_kernel<<<dim3(DFF_ / 32, D_ / 32), 256>>>(w1, w1t, D_, DFF_);
    wcast_kernel<<<dim3(D_ / 32, DFF_ / 32), 256>>>(w2, w2t, DFF_, D_);

    // 1) LN1 -> fp16
    ln_f16_kernel<<<NTOK / 8, 256>>>(x, ln1_g, ln1_b, h);
    // 2) QKV projection -> fp16
    gemm_mma<3><<<dim3(D3_ / BN, NTOK / BM), 256, GEMM_SMEM>>>(
        h, wq, b_qkv, nullptr, nullptr, qkvh, NTOK, D3_, D_);
    // 3) attention + residual -> x1
    flash_mma<<<dim3(P_ / FQT, H_, B_), 128, FLASH_SMEM>>>(qkvh, x, x1);
    // 4) LN2 -> fp16
    ln_f16_kernel<<<NTOK / 8, 256>>>(x1, ln2_g, ln2_b, h);
    // 5) MLP up + GELU -> fp16
    gemm_mma<1><<<dim3(DFF_ / BN, NTOK / BM), 256, GEMM_SMEM>>>(
        h, w1t, b1, nullptr, nullptr, ffn, NTOK, DFF_, D_);
    // 6) MLP down + droppath + residual -> out
    gemm_mma<2><<<dim3(D_ / BN, NTOK / BM), 256, GEMM_SMEM>>>(
        ffn, w2t, b2, x1, out, nullptr, NTOK, D_, DFF_);
}